// round 1
// baseline (speedup 1.0000x reference)
#include <cuda_runtime.h>

#define NN 10000
#define EE 50000
#define IND 8
#define EDD 4
#define H 64
#define HH 4096
#define KH 32
#define GEPS 1e-5f

// ---------------- device scratch (static, no allocation) ----------------
__device__ float g_h[NN * H];        // current node features
__device__ float g_hpre[NN * H];     // pre-norm features
__device__ float g_base[NN * H];     // h@(B2+root_w)+root_b
__device__ float g_agg[NN * H];      // scatter accumulator
__device__ float g_r[EE * KH];       // edge MLP hidden (post-ReLU)
__device__ float g_G[NN * KH * H];   // per-node contracted tensor [n][k][o]  (82 MB, fits L2)
__device__ int   g_deg[NN];
__device__ float g_invdeg[NN];
__device__ float g_colsum[H];
__device__ float g_colsumsq[H];
__device__ float g_ga[H];
__device__ float g_gc[H];

// ---------------- kernels ----------------
__global__ void k_zero_deg() {
    int i = blockIdx.x * blockDim.x + threadIdx.x;
    if (i < NN) g_deg[i] = 0;
}

__global__ void k_count(const int* __restrict__ dst) {
    int i = blockIdx.x * blockDim.x + threadIdx.x;
    if (i < EE) atomicAdd(&g_deg[dst[i]], 1);
}

__global__ void k_inv() {
    int i = blockIdx.x * blockDim.x + threadIdx.x;
    if (i < NN) g_invdeg[i] = 1.0f / fmaxf((float)g_deg[i], 1.0f);
}

// h = x @ proj_w + proj_b
__global__ void k_proj(const float* __restrict__ x, const float* __restrict__ w,
                       const float* __restrict__ b) {
    int idx = blockIdx.x * blockDim.x + threadIdx.x;
    if (idx >= NN * H) return;
    int n = idx >> 6, o = idx & 63;
    float acc = b[o];
#pragma unroll
    for (int i = 0; i < IND; i++) acc += x[n * IND + i] * w[i * H + o];
    g_h[idx] = acc;
}

__global__ void k_zero_layer() {
    int idx = blockIdx.x * blockDim.x + threadIdx.x;
    if (idx < NN * H) g_agg[idx] = 0.0f;
    if (idx < H) g_colsum[idx] = 0.0f;
    else if (idx < 2 * H) g_colsumsq[idx - H] = 0.0f;
}

// r = relu(edge_attr @ W1 + b1)   [E, 32]
__global__ void k_edge_mlp(const float* __restrict__ ea, const float* __restrict__ w1,
                           const float* __restrict__ b1) {
    int idx = blockIdx.x * blockDim.x + threadIdx.x;
    if (idx >= EE * KH) return;
    int e = idx >> 5, k = idx & 31;
    float acc = b1[k];
#pragma unroll
    for (int d = 0; d < EDD; d++) acc += ea[e * EDD + d] * w1[d * KH + k];
    g_r[idx] = fmaxf(acc, 0.0f);
}

// G[n, k*64+o] = sum_i h[n,i] * W2[k, i*64+o]
// Block (bx, k): 64 nodes x 64 o-cols. B tile = W2 + k*4096, contiguous [i][o].
__global__ __launch_bounds__(256) void k_G(const float* __restrict__ w2) {
    __shared__ float As[64][65];
    __shared__ float Bs[64][65];
    int n0 = blockIdx.x * 64;
    int k = blockIdx.y;
    const float* B = w2 + k * HH;
    int tid = threadIdx.x;
    for (int t = tid; t < 4096; t += 256) {
        int r = t >> 6, c = t & 63;
        int n = n0 + r;
        As[r][c] = (n < NN) ? g_h[n * H + c] : 0.0f;
        Bs[r][c] = B[t];
    }
    __syncthreads();
    int ty = tid >> 4, tx = tid & 15;
    float acc[4][4] = {};
#pragma unroll 8
    for (int i = 0; i < 64; i++) {
        float a[4], b[4];
#pragma unroll
        for (int u = 0; u < 4; u++) { a[u] = As[ty * 4 + u][i]; b[u] = Bs[i][tx * 4 + u]; }
#pragma unroll
        for (int u = 0; u < 4; u++)
#pragma unroll
            for (int v = 0; v < 4; v++) acc[u][v] += a[u] * b[v];
    }
#pragma unroll
    for (int u = 0; u < 4; u++) {
        int n = n0 + ty * 4 + u;
        if (n < NN) {
#pragma unroll
            for (int v = 0; v < 4; v++)
                g_G[(size_t)n * (KH * H) + k * H + tx * 4 + v] = acc[u][v];
        }
    }
}

// base = h @ (B2 + root_w) + root_b  (16 nodes per block)
__global__ __launch_bounds__(256) void k_base(const float* __restrict__ b2,
                                              const float* __restrict__ rw,
                                              const float* __restrict__ rb) {
    __shared__ float W[HH];
    __shared__ float hs[4 * 64];
    int tid = threadIdx.x;
    for (int t = tid; t < HH; t += 256) W[t] = b2[t] + rw[t];
    int o = tid & 63, g = tid >> 6;
    float bias = rb[o];
    for (int j = 0; j < 4; j++) {
        int n = blockIdx.x * 16 + j * 4 + g;
        __syncthreads();
        hs[tid] = (n < NN) ? g_h[n * H + o] : 0.0f;
        __syncthreads();
        if (n < NN) {
            float acc = bias;
#pragma unroll
            for (int i = 0; i < H; i++) acc += hs[g * 64 + i] * W[i * H + o];
            g_base[n * H + o] = acc;
        }
    }
}

// per-edge: msg = r_e @ G[src], atomic scatter into agg[dst]. One warp per edge.
__global__ __launch_bounds__(256) void k_msg(const int* __restrict__ src,
                                             const int* __restrict__ dst) {
    int e = (blockIdx.x << 3) + (threadIdx.x >> 5);
    int lane = threadIdx.x & 31;
    if (e >= EE) return;
    int s = src[e], d = dst[e];
    float rk = g_r[e * KH + lane];
    const float* Gr = g_G + (size_t)s * (KH * H);
    float a0 = 0.0f, a1 = 0.0f;
#pragma unroll
    for (int k = 0; k < KH; k++) {
        float rv = __shfl_sync(0xffffffffu, rk, k);
        a0 += rv * Gr[k * H + lane];
        a1 += rv * Gr[k * H + 32 + lane];
    }
    atomicAdd(&g_agg[d * H + lane], a0);
    atomicAdd(&g_agg[d * H + 32 + lane], a1);
}

// h_pre = agg*invdeg + base; accumulate per-column sum / sumsq
__global__ __launch_bounds__(256) void k_pass1() {
    __shared__ float rs[256], rs2[256];
    int tid = threadIdx.x;
    int o = tid & 63, g = tid >> 6;
    float s = 0.0f, s2 = 0.0f;
    int nbase = blockIdx.x * 64;
    for (int j = 0; j < 16; j++) {
        int n = nbase + j * 4 + g;
        if (n < NN) {
            int idx = n * H + o;
            float v = g_agg[idx] * g_invdeg[n] + g_base[idx];
            g_hpre[idx] = v;
            s += v;
            s2 += v * v;
        }
    }
    rs[tid] = s;
    rs2[tid] = s2;
    __syncthreads();
    if (tid < 64) {
        float t = rs[tid] + rs[tid + 64] + rs[tid + 128] + rs[tid + 192];
        float t2 = rs2[tid] + rs2[tid + 64] + rs2[tid + 128] + rs2[tid + 192];
        atomicAdd(&g_colsum[tid], t);
        atomicAdd(&g_colsumsq[tid], t2);
    }
}

// GraphNorm affine fold: out = a*h + c
__global__ void k_finalize(const float* __restrict__ gw, const float* __restrict__ gb,
                           const float* __restrict__ gms) {
    int o = threadIdx.x;
    float mean = g_colsum[o] * (1.0f / NN);
    float ex2 = g_colsumsq[o] * (1.0f / NN);
    float ms = gms[o];
    float var = ex2 - (2.0f * ms - ms * ms) * mean * mean;
    float a = gw[o] * rsqrtf(var + GEPS);
    g_ga[o] = a;
    g_gc[o] = gb[o] - a * ms * mean;
}

__global__ void k_pass2(int to_out, float* __restrict__ out, int leaky) {
    int idx = blockIdx.x * blockDim.x + threadIdx.x;
    if (idx >= NN * H) return;
    int o = idx & 63;
    float v = g_ga[o] * g_hpre[idx] + g_gc[o];
    if (leaky) v = (v > 0.0f) ? v : 0.2f * v;
    if (to_out) out[idx] = v;
    else g_h[idx] = v;
}

// ---------------- launch ----------------
extern "C" void kernel_launch(void* const* d_in, const int* in_sizes, int n_in,
                              void* d_out, int out_size) {
    const float* x      = (const float*)d_in[0];
    const int*   ei     = (const int*)d_in[1];
    const float* ea     = (const float*)d_in[2];
    const float* proj_w = (const float*)d_in[3];
    const float* proj_b = (const float*)d_in[4];
    const float* enn_w1 = (const float*)d_in[5];
    const float* enn_b1 = (const float*)d_in[6];
    const float* enn_w2 = (const float*)d_in[7];
    const float* enn_b2 = (const float*)d_in[8];
    const float* root_w = (const float*)d_in[9];
    const float* root_b = (const float*)d_in[10];
    const float* gn_w   = (const float*)d_in[11];
    const float* gn_b   = (const float*)d_in[12];
    const float* gn_ms  = (const float*)d_in[13];
    const int* src = ei;
    const int* dst = ei + EE;

    k_zero_deg<<<(NN + 255) / 256, 256>>>();
    k_count<<<(EE + 255) / 256, 256>>>(dst);
    k_inv<<<(NN + 255) / 256, 256>>>();
    k_proj<<<(NN * H + 255) / 256, 256>>>(x, proj_w, proj_b);

    for (int l = 0; l < 2; l++) {
        k_zero_layer<<<(NN * H + 255) / 256, 256>>>();
        k_edge_mlp<<<(EE * KH + 255) / 256, 256>>>(ea, enn_w1 + l * (EDD * KH),
                                                   enn_b1 + l * KH);
        k_G<<<dim3((NN + 63) / 64, KH), 256>>>(enn_w2 + (size_t)l * (KH * HH));
        k_base<<<(NN + 15) / 16, 256>>>(enn_b2 + l * HH, root_w + l * HH,
                                        root_b + l * H);
        k_msg<<<(EE + 7) / 8, 256>>>(src, dst);
        k_pass1<<<(NN + 63) / 64, 256>>>();
        k_finalize<<<1, 64>>>(gn_w + l * H, gn_b + l * H, gn_ms + l * H);
        k_pass2<<<(NN * H + 255) / 256, 256>>>(l == 1 ? 1 : 0, (float*)d_out,
                                               l == 0 ? 1 : 0);
    }
}

// round 3
// speedup vs baseline: 1.3969x; 1.3969x over previous
#include <cuda_runtime.h>
#include <cuda_bf16.h>
#include <cstdint>

#define NN 10000
#define MPAD 10112           // 79 * 128
#define EE 50000
#define IND 8
#define H 64
#define KH 32
#define KB 192               // stacked K: [h_hi | h_hi | h_lo]
#define NB 2176              // 2048 (G) + 64 (root_w base) + 64 (B2 u-term)
#define GEPS 1e-5f

// ===================== device scratch =====================
__device__ float g_h[NN * H];
__device__ float g_hpre[NN * H];
__device__ float g_agg[NN * H];
__device__ float g_r[2 * EE * KH];
__device__ __nv_bfloat16 g_A[MPAD * KB];            // [h_hi | h_hi | h_lo]
__device__ __nv_bfloat16 g_B[2 * NB * KB];          // per-layer [N-row][K] bf16
__device__ float g_GB[(size_t)MPAD * NB];           // GEMM output: G | base | u
__device__ int g_sdeg[NN], g_ddeg[NN];
__device__ int g_soff[NN + 1], g_cursor[NN], g_csr[EE];
__device__ float g_invdeg[NN];
__device__ float g_colsum[H], g_colsumsq[H];
__device__ float g_ga[H], g_gc[H];

// ===================== setup kernels =====================
__global__ void k_zero() {
    int i = blockIdx.x * blockDim.x + threadIdx.x;
    if (i < NN) { g_sdeg[i] = 0; g_ddeg[i] = 0; }
    if (i < H) { g_colsum[i] = 0.0f; g_colsumsq[i] = 0.0f; }
}
__global__ void k_count(const int* __restrict__ src, const int* __restrict__ dst) {
    int i = blockIdx.x * blockDim.x + threadIdx.x;
    if (i < EE) { atomicAdd(&g_sdeg[src[i]], 1); atomicAdd(&g_ddeg[dst[i]], 1); }
}
__global__ void k_scan() {  // single block, 1024 threads
    __shared__ int sbuf[1024];
    int tid = threadIdx.x;
    int run = 0;
    for (int ch = 0; ch < 10; ch++) {
        int i = ch * 1024 + tid;
        int v = (i < NN) ? g_sdeg[i] : 0;
        sbuf[tid] = v;
        __syncthreads();
        for (int ofs = 1; ofs < 1024; ofs <<= 1) {
            int t = (tid >= ofs) ? sbuf[tid - ofs] : 0;
            __syncthreads();
            sbuf[tid] += t;
            __syncthreads();
        }
        int excl = sbuf[tid] - v;
        if (i < NN) { g_soff[i] = run + excl; g_cursor[i] = run + excl; }
        run += sbuf[1023];
        __syncthreads();
    }
    if (tid == 0) g_soff[NN] = run;
    for (int i = tid; i < NN; i += 1024)
        g_invdeg[i] = 1.0f / fmaxf((float)g_ddeg[i], 1.0f);
}
__global__ void k_fill(const int* __restrict__ src) {
    int e = blockIdx.x * blockDim.x + threadIdx.x;
    if (e < EE) {
        int pos = atomicAdd(&g_cursor[src[e]], 1);
        g_csr[pos] = e;
    }
}
// h = x @ proj_w + proj_b ; zero agg for layer 0
__global__ void k_proj(const float* __restrict__ x, const float* __restrict__ w,
                       const float* __restrict__ b) {
    int idx = blockIdx.x * blockDim.x + threadIdx.x;
    if (idx >= NN * H) return;
    int n = idx >> 6, o = idx & 63;
    float acc = b[o];
#pragma unroll
    for (int i = 0; i < IND; i++) acc += x[n * IND + i] * w[i * H + o];
    g_h[idx] = acc;
    g_agg[idx] = 0.0f;
}
// r = relu(edge_attr @ W1 + b1) for BOTH layers
__global__ void k_mlp(const float* __restrict__ ea, const float* __restrict__ w1,
                      const float* __restrict__ b1) {
    int idx = blockIdx.x * blockDim.x + threadIdx.x;
    if (idx >= 2 * EE * KH) return;
    int l = idx / (EE * KH);
    int rem = idx - l * (EE * KH);
    int e = rem >> 5, k = rem & 31;
    float acc = b1[l * KH + k];
#pragma unroll
    for (int d = 0; d < 4; d++) acc += ea[e * 4 + d] * w1[l * 128 + d * KH + k];
    g_r[idx] = fmaxf(acc, 0.0f);
}
// Build B [l][c=0..2175][k=0..191]: K-blocks {hi(W), lo(W), hi(W)}
__global__ void k_Bprep(const float* __restrict__ w2, const float* __restrict__ rw,
                        const float* __restrict__ b2) {
    int idx = blockIdx.x * blockDim.x + threadIdx.x;
    if (idx >= 2 * NB * KB) return;
    int l = idx / (NB * KB);
    int rem = idx - l * (NB * KB);
    int c = rem / KB, k = rem - c * KB;
    int blk = k >> 6, i = k & 63;
    float S;
    if (c < 2048) S = w2[l * 131072 + (c >> 6) * 4096 + i * 64 + (c & 63)];
    else if (c < 2112) S = rw[l * 4096 + i * 64 + (c - 2048)];
    else S = b2[l * 4096 + i * 64 + (c - 2112)];
    __nv_bfloat16 hi = __float2bfloat16(S);
    __nv_bfloat16 v = (blk == 1) ? __float2bfloat16(S - __bfloat162float(hi)) : hi;
    g_B[idx] = v;
}
// A [n][0:64]=hi(h), [64:128]=hi(h), [128:192]=lo(h); zero padding rows
__global__ void k_Aprep() {
    int idx = blockIdx.x * blockDim.x + threadIdx.x;
    if (idx >= MPAD * H) return;
    int n = idx >> 6, i = idx & 63;
    float v = (n < NN) ? g_h[n * H + i] : 0.0f;
    __nv_bfloat16 hi = __float2bfloat16(v);
    __nv_bfloat16 lo = __float2bfloat16(v - __bfloat162float(hi));
    g_A[n * KB + i] = hi;
    g_A[n * KB + 64 + i] = hi;
    g_A[n * KB + 128 + i] = lo;
}

// ===================== warp-MMA GEMM: C[10112, 2176] = A[.,192] @ B^T =====================
__device__ __forceinline__ void mma_bf16(float* c, const uint32_t* a, const uint32_t* b) {
    asm volatile(
        "mma.sync.aligned.m16n8k16.row.col.f32.bf16.bf16.f32 "
        "{%0,%1,%2,%3}, {%4,%5,%6,%7}, {%8,%9}, {%0,%1,%2,%3};"
        : "+f"(c[0]), "+f"(c[1]), "+f"(c[2]), "+f"(c[3])
        : "r"(a[0]), "r"(a[1]), "r"(a[2]), "r"(a[3]), "r"(b[0]), "r"(b[1]));
}

#define SSTR 72   // smem K-stride (bf16 elems): pad 64->72 keeps 16B align, kills bank conflicts
__global__ __launch_bounds__(256) void k_gemm(int layer) {
    __shared__ __nv_bfloat16 sA[128 * SSTR];
    __shared__ __nv_bfloat16 sB[128 * SSTR];
    int tid = threadIdx.x;
    int lane = tid & 31, w = tid >> 5;
    int wm = w >> 1, wn = w & 1;           // 4x2 warp grid
    int g = lane >> 2, tc = lane & 3;
    int n0 = blockIdx.x * 128, nb0 = blockIdx.y * 128;
    const __nv_bfloat16* Bg = g_B + (size_t)layer * NB * KB;

    float acc[2][8][4] = {};
    for (int c = 0; c < 3; c++) {
        __syncthreads();
        for (int u = tid; u < 1024; u += 256) {
            int r = u >> 3, j = u & 7;
            *(uint4*)(sA + r * SSTR + j * 8) =
                *(const uint4*)(g_A + (size_t)(n0 + r) * KB + c * 64 + j * 8);
            *(uint4*)(sB + r * SSTR + j * 8) =
                *(const uint4*)(Bg + (size_t)(nb0 + r) * KB + c * 64 + j * 8);
        }
        __syncthreads();
#pragma unroll
        for (int ks = 0; ks < 4; ks++) {
            uint32_t af[2][4], bf[8][2];
#pragma unroll
            for (int mi = 0; mi < 2; mi++) {
                const __nv_bfloat16* pa = sA + ks * 16 + tc * 2;
                int rb = wm * 32 + mi * 16;
                af[mi][0] = *(const uint32_t*)(pa + (rb + g) * SSTR);
                af[mi][1] = *(const uint32_t*)(pa + (rb + g + 8) * SSTR);
                af[mi][2] = *(const uint32_t*)(pa + (rb + g) * SSTR + 8);
                af[mi][3] = *(const uint32_t*)(pa + (rb + g + 8) * SSTR + 8);
            }
#pragma unroll
            for (int ni = 0; ni < 8; ni++) {
                const __nv_bfloat16* pb = sB + (wn * 64 + ni * 8 + g) * SSTR + ks * 16 + tc * 2;
                bf[ni][0] = *(const uint32_t*)pb;
                bf[ni][1] = *(const uint32_t*)(pb + 8);
            }
#pragma unroll
            for (int mi = 0; mi < 2; mi++)
#pragma unroll
                for (int ni = 0; ni < 8; ni++)
                    mma_bf16(acc[mi][ni], af[mi], bf[ni]);
        }
    }
    // epilogue: fragment-mapped direct stores
#pragma unroll
    for (int mi = 0; mi < 2; mi++) {
        int row0 = n0 + wm * 32 + mi * 16 + g;
#pragma unroll
        for (int ni = 0; ni < 8; ni++) {
            int col = nb0 + wn * 64 + ni * 8 + tc * 2;
            *(float2*)(g_GB + (size_t)row0 * NB + col) =
                make_float2(acc[mi][ni][0], acc[mi][ni][1]);
            *(float2*)(g_GB + (size_t)(row0 + 8) * NB + col) =
                make_float2(acc[mi][ni][2], acc[mi][ni][3]);
        }
    }
}

// ===================== message pass: warp per src node, G row in registers =====================
__global__ __launch_bounds__(256) void k_msg(const int* __restrict__ dst, int layer) {
    int w = blockIdx.x * 8 + (threadIdx.x >> 5);
    int lane = threadIdx.x & 31;
    if (w >= NN) return;
    int beg = g_soff[w], end = g_soff[w + 1];
    if (beg == end) return;
    const float* row = g_GB + (size_t)w * NB;
    float G0[32], G1[32];
#pragma unroll
    for (int k = 0; k < 32; k++) {
        G0[k] = row[k * 64 + lane];
        G1[k] = row[k * 64 + 32 + lane];
    }
    float u0 = row[2112 + lane], u1 = row[2144 + lane];
    const float* rbase = g_r + (size_t)layer * EE * KH;
    for (int p = beg; p < end; p++) {
        int e = g_csr[p];
        int d = dst[e];
        float rk = rbase[e * KH + lane];
        float a0 = u0, a1 = u1;
#pragma unroll
        for (int k = 0; k < 32; k++) {
            float rv = __shfl_sync(0xffffffffu, rk, k);
            a0 += rv * G0[k];
            a1 += rv * G1[k];
        }
        atomicAdd(&g_agg[d * H + lane], a0);
        atomicAdd(&g_agg[d * H + 32 + lane], a1);
    }
}

// ===================== norm passes =====================
__global__ __launch_bounds__(256) void k_pass1(const float* __restrict__ rb) {
    __shared__ float rs[256], rs2[256];
    int tid = threadIdx.x;
    int o = tid & 63, g = tid >> 6;
    float s = 0.0f, s2 = 0.0f;
    int nbase = blockIdx.x * 64;
    for (int j = 0; j < 16; j++) {
        int n = nbase + j * 4 + g;
        if (n < NN) {
            int idx = n * H + o;
            float v = g_agg[idx] * g_invdeg[n] + g_GB[(size_t)n * NB + 2048 + o] + rb[o];
            g_hpre[idx] = v;
            s += v;
            s2 += v * v;
        }
    }
    rs[tid] = s;
    rs2[tid] = s2;
    __syncthreads();
    if (tid < 64) {
        float t = rs[tid] + rs[tid + 64] + rs[tid + 128] + rs[tid + 192];
        float t2 = rs2[tid] + rs2[tid + 64] + rs2[tid + 128] + rs2[tid + 192];
        atomicAdd(&g_colsum[tid], t);
        atomicAdd(&g_colsumsq[tid], t2);
    }
}
__global__ void k_finalize(const float* __restrict__ gw, const float* __restrict__ gb,
                           const float* __restrict__ gms) {
    int o = threadIdx.x;
    float mean = g_colsum[o] * (1.0f / NN);
    float ex2 = g_colsumsq[o] * (1.0f / NN);
    float ms = gms[o];
    float var = ex2 - (2.0f * ms - ms * ms) * mean * mean;
    float a = gw[o] * rsqrtf(var + GEPS);
    g_ga[o] = a;
    g_gc[o] = gb[o] - a * ms * mean;
}
__global__ void k_pass2(int l, float* __restrict__ out) {
    int idx = blockIdx.x * blockDim.x + threadIdx.x;
    if (idx >= NN * H) return;
    int o = idx & 63;
    float v = g_ga[o] * g_hpre[idx] + g_gc[o];
    if (l == 0) {
        v = (v > 0.0f) ? v : 0.2f * v;       // LeakyReLU between layers
        g_h[idx] = v;
        g_agg[idx] = 0.0f;                    // zero agg for next layer
        if (idx < H) g_colsum[idx] = 0.0f;
        else if (idx < 2 * H) g_colsumsq[idx - H] = 0.0f;
    } else {
        out[idx] = v;
    }
}

// ===================== launch =====================
extern "C" void kernel_launch(void* const* d_in, const int* in_sizes, int n_in,
                              void* d_out, int out_size) {
    const float* x      = (const float*)d_in[0];
    const int*   ei     = (const int*)d_in[1];
    const float* ea     = (const float*)d_in[2];
    const float* proj_w = (const float*)d_in[3];
    const float* proj_b = (const float*)d_in[4];
    const float* enn_w1 = (const float*)d_in[5];
    const float* enn_b1 = (const float*)d_in[6];
    const float* enn_w2 = (const float*)d_in[7];
    const float* enn_b2 = (const float*)d_in[8];
    const float* root_w = (const float*)d_in[9];
    const float* root_b = (const float*)d_in[10];
    const float* gn_w   = (const float*)d_in[11];
    const float* gn_b   = (const float*)d_in[12];
    const float* gn_ms  = (const float*)d_in[13];
    const int* src = ei;
    const int* dst = ei + EE;

    k_zero<<<(NN + 255) / 256, 256>>>();
    k_count<<<(EE + 255) / 256, 256>>>(src, dst);
    k_scan<<<1, 1024>>>();
    k_fill<<<(EE + 255) / 256, 256>>>(src);
    k_proj<<<(NN * H + 255) / 256, 256>>>(x, proj_w, proj_b);
    k_mlp<<<(2 * EE * KH + 255) / 256, 256>>>(ea, enn_w1, enn_b1);
    k_Bprep<<<(2 * NB * KB + 255) / 256, 256>>>(enn_w2, root_w, enn_b2);

    for (int l = 0; l < 2; l++) {
        k_Aprep<<<(MPAD * H + 255) / 256, 256>>>();
        k_gemm<<<dim3(79, 17), 256>>>(l);
        k_msg<<<(NN + 7) / 8, 256>>>(dst, l);
        k_pass1<<<(NN + 63) / 64, 256>>>(root_b + l * H);
        k_finalize<<<1, 64>>>(gn_w + l * H, gn_b + l * H, gn_ms + l * H);
        k_pass2<<<(NN * H + 255) / 256, 256>>>(l, (float*)d_out);
    }
}

// round 4
// speedup vs baseline: 1.4299x; 1.0236x over previous
#include <cuda_runtime.h>
#include <cuda_bf16.h>
#include <cstdint>

#define NN 10000
#define MPAD 10112           // 79 * 128
#define EE 50000
#define IND 8
#define H 64
#define KH 32
#define KB 192               // stacked K: [h_hi | h_hi | h_lo]
#define NB 2176              // 2048 (G) + 64 (root_w base) + 64 (B2 u-term)
#define GEPS 1e-5f

// ===================== device scratch =====================
__device__ float g_hpre[NN * H];
__device__ float g_agg[NN * H];
__device__ float g_r[2 * EE * KH];
__device__ __nv_bfloat16 g_A[MPAD * KB];            // [h_hi | h_hi | h_lo]
__device__ __nv_bfloat16 g_B[2 * NB * KB];          // per-layer [N-row][K] bf16
__device__ float g_GB[(size_t)MPAD * NB];           // GEMM output: G | base | u
__device__ int g_sdeg[NN], g_ddeg[NN];
__device__ int g_soff[NN + 1], g_cursor[NN], g_csr[EE];
__device__ float g_invdeg[NN];
__device__ float g_colsum[H], g_colsumsq[H];
__device__ float g_ga[H], g_gc[H];

__device__ __forceinline__ uint32_t smem_u32(const void* p) {
    uint32_t a;
    asm("{ .reg .u64 t; cvta.to.shared.u64 t, %1; cvt.u32.u64 %0, t; }" : "=r"(a) : "l"(p));
    return a;
}

// ===================== setup kernels =====================
__global__ void k_zero() {
    int i = blockIdx.x * blockDim.x + threadIdx.x;
    if (i < NN) { g_sdeg[i] = 0; g_ddeg[i] = 0; }
    if (i < H) { g_colsum[i] = 0.0f; g_colsumsq[i] = 0.0f; }
}
__global__ void k_count(const int* __restrict__ src, const int* __restrict__ dst) {
    int i = blockIdx.x * blockDim.x + threadIdx.x;
    if (i < EE) { atomicAdd(&g_sdeg[src[i]], 1); atomicAdd(&g_ddeg[dst[i]], 1); }
}
__global__ void k_scan() {  // single block, 1024 threads
    __shared__ int sbuf[1024];
    int tid = threadIdx.x;
    int run = 0;
    for (int ch = 0; ch < 10; ch++) {
        int i = ch * 1024 + tid;
        int v = (i < NN) ? g_sdeg[i] : 0;
        sbuf[tid] = v;
        __syncthreads();
        for (int ofs = 1; ofs < 1024; ofs <<= 1) {
            int t = (tid >= ofs) ? sbuf[tid - ofs] : 0;
            __syncthreads();
            sbuf[tid] += t;
            __syncthreads();
        }
        int excl = sbuf[tid] - v;
        if (i < NN) { g_soff[i] = run + excl; g_cursor[i] = run + excl; }
        run += sbuf[1023];
        __syncthreads();
    }
    if (tid == 0) g_soff[NN] = run;
    for (int i = tid; i < NN; i += 1024)
        g_invdeg[i] = 1.0f / fmaxf((float)g_ddeg[i], 1.0f);
}
__global__ void k_fill(const int* __restrict__ src) {
    int e = blockIdx.x * blockDim.x + threadIdx.x;
    if (e < EE) {
        int pos = atomicAdd(&g_cursor[src[e]], 1);
        g_csr[pos] = e;
    }
}
// h = x@proj_w+proj_b, directly split into g_A [hi|hi|lo]; zero agg; pad rows zeroed
__global__ void k_proj(const float* __restrict__ x, const float* __restrict__ w,
                       const float* __restrict__ b) {
    int idx = blockIdx.x * blockDim.x + threadIdx.x;
    if (idx >= MPAD * H) return;
    int n = idx >> 6, o = idx & 63;
    float v = 0.0f;
    if (n < NN) {
        v = b[o];
#pragma unroll
        for (int i = 0; i < IND; i++) v += x[n * IND + i] * w[i * H + o];
        g_agg[idx] = 0.0f;
    }
    __nv_bfloat16 hi = __float2bfloat16(v);
    __nv_bfloat16 lo = __float2bfloat16(v - __bfloat162float(hi));
    g_A[n * KB + o] = hi;
    g_A[n * KB + 64 + o] = hi;
    g_A[n * KB + 128 + o] = lo;
}
// r = relu(edge_attr @ W1 + b1) for BOTH layers
__global__ void k_mlp(const float* __restrict__ ea, const float* __restrict__ w1,
                      const float* __restrict__ b1) {
    int idx = blockIdx.x * blockDim.x + threadIdx.x;
    if (idx >= 2 * EE * KH) return;
    int l = idx / (EE * KH);
    int rem = idx - l * (EE * KH);
    int e = rem >> 5, k = rem & 31;
    float acc = b1[l * KH + k];
#pragma unroll
    for (int d = 0; d < 4; d++) acc += ea[e * 4 + d] * w1[l * 128 + d * KH + k];
    g_r[idx] = fmaxf(acc, 0.0f);
}
// Build B [l][c][k]: K-blocks {hi(W), lo(W), hi(W)}
__global__ void k_Bprep(const float* __restrict__ w2, const float* __restrict__ rw,
                        const float* __restrict__ b2) {
    int idx = blockIdx.x * blockDim.x + threadIdx.x;
    if (idx >= 2 * NB * KB) return;
    int l = idx / (NB * KB);
    int rem = idx - l * (NB * KB);
    int c = rem / KB, k = rem - c * KB;
    int blk = k >> 6, i = k & 63;
    float S;
    if (c < 2048) S = w2[l * 131072 + (c >> 6) * 4096 + i * 64 + (c & 63)];
    else if (c < 2112) S = rw[l * 4096 + i * 64 + (c - 2048)];
    else S = b2[l * 4096 + i * 64 + (c - 2112)];
    __nv_bfloat16 hi = __float2bfloat16(S);
    __nv_bfloat16 v = (blk == 1) ? __float2bfloat16(S - __bfloat162float(hi)) : hi;
    g_B[idx] = v;
}

// ===================== warp-MMA GEMM, cp.async 2-stage pipeline =====================
__device__ __forceinline__ void mma_bf16(float* c, const uint32_t* a, const uint32_t* b) {
    asm volatile(
        "mma.sync.aligned.m16n8k16.row.col.f32.bf16.bf16.f32 "
        "{%0,%1,%2,%3}, {%4,%5,%6,%7}, {%8,%9}, {%0,%1,%2,%3};"
        : "+f"(c[0]), "+f"(c[1]), "+f"(c[2]), "+f"(c[3])
        : "r"(a[0]), "r"(a[1]), "r"(a[2]), "r"(a[3]), "r"(b[0]), "r"(b[1]));
}
__device__ __forceinline__ void cp16(uint32_t sdst, const void* gsrc) {
    asm volatile("cp.async.ca.shared.global [%0], [%1], 16;" :: "r"(sdst), "l"(gsrc));
}
#define CPCOMMIT() asm volatile("cp.async.commit_group;" ::: "memory")
#define CPWAIT1() asm volatile("cp.async.wait_group 1;" ::: "memory")

#define CH 32      // K elems per chunk (6 chunks)
#define SSTR 40    // smem row stride (bf16 elems) = 80B; banks (20g+tc)%32 all distinct

__global__ __launch_bounds__(256) void k_gemm(int layer) {
    __shared__ __nv_bfloat16 sA[2][128 * SSTR];
    __shared__ __nv_bfloat16 sB[2][128 * SSTR];
    int tid = threadIdx.x;
    int lane = tid & 31, w = tid >> 5;
    int wm = w >> 1, wn = w & 1;           // 4x2 warp grid
    int g = lane >> 2, tc = lane & 3;
    int n0 = blockIdx.x * 128, nb0 = blockIdx.y * 128;
    const __nv_bfloat16* Bg = g_B + (size_t)layer * NB * KB;

    // per-thread copy slots: 4 transfers/chunk (2 A rows-quarters, 2 B)
    int r = tid >> 1;               // 0..127
    int jj = (tid & 1) * 2;         // 0 or 2 (two 16B chunks each)
    uint32_t dA0 = smem_u32(&sA[0][r * SSTR + jj * 8]);
    uint32_t dB0 = smem_u32(&sB[0][r * SSTR + jj * 8]);
    const __nv_bfloat16* gA = g_A + (size_t)(n0 + r) * KB + jj * 8;
    const __nv_bfloat16* gBp = Bg + (size_t)(nb0 + r) * KB + jj * 8;
    const uint32_t stgofs = 128 * SSTR * 2;  // bytes between stages

#define ISSUE(c, st) do {                                           \
        uint32_t o = (st) * stgofs;                                 \
        cp16(dA0 + o, gA + (c) * CH);                               \
        cp16(dA0 + o + 16, gA + (c) * CH + 8);                      \
        cp16(dB0 + o, gBp + (c) * CH);                              \
        cp16(dB0 + o + 16, gBp + (c) * CH + 8);                     \
    } while (0)

    ISSUE(0, 0); CPCOMMIT();
    ISSUE(1, 1); CPCOMMIT();

    float acc[2][8][4] = {};
#pragma unroll
    for (int c = 0; c < 6; c++) {
        CPWAIT1();
        __syncthreads();
        int st = c & 1;
#pragma unroll
        for (int ks = 0; ks < 2; ks++) {
            uint32_t af[2][4], bf[8][2];
#pragma unroll
            for (int mi = 0; mi < 2; mi++) {
                const __nv_bfloat16* pa = sA[st] + ks * 16 + tc * 2;
                int rb = wm * 32 + mi * 16;
                af[mi][0] = *(const uint32_t*)(pa + (rb + g) * SSTR);
                af[mi][1] = *(const uint32_t*)(pa + (rb + g + 8) * SSTR);
                af[mi][2] = *(const uint32_t*)(pa + (rb + g) * SSTR + 8);
                af[mi][3] = *(const uint32_t*)(pa + (rb + g + 8) * SSTR + 8);
            }
#pragma unroll
            for (int ni = 0; ni < 8; ni++) {
                const __nv_bfloat16* pb = sB[st] + (wn * 64 + ni * 8 + g) * SSTR + ks * 16 + tc * 2;
                bf[ni][0] = *(const uint32_t*)pb;
                bf[ni][1] = *(const uint32_t*)(pb + 8);
            }
#pragma unroll
            for (int mi = 0; mi < 2; mi++)
#pragma unroll
                for (int ni = 0; ni < 8; ni++)
                    mma_bf16(acc[mi][ni], af[mi], bf[ni]);
        }
        __syncthreads();
        if (c + 2 < 6) ISSUE(c + 2, st);
        CPCOMMIT();
    }
    // epilogue: fragment-mapped direct stores
#pragma unroll
    for (int mi = 0; mi < 2; mi++) {
        int row0 = n0 + wm * 32 + mi * 16 + g;
#pragma unroll
        for (int ni = 0; ni < 8; ni++) {
            int col = nb0 + wn * 64 + ni * 8 + tc * 2;
            *(float2*)(g_GB + (size_t)row0 * NB + col) =
                make_float2(acc[mi][ni][0], acc[mi][ni][1]);
            *(float2*)(g_GB + (size_t)(row0 + 8) * NB + col) =
                make_float2(acc[mi][ni][2], acc[mi][ni][3]);
        }
    }
#undef ISSUE
}

// ===================== message pass: warp per src node, G row in registers =====================
__global__ __launch_bounds__(256) void k_msg(const int* __restrict__ dst, int layer) {
    int w = blockIdx.x * 8 + (threadIdx.x >> 5);
    int lane = threadIdx.x & 31;
    if (w >= NN) return;
    int beg = g_soff[w], end = g_soff[w + 1];
    if (beg == end) return;
    const float* row = g_GB + (size_t)w * NB;
    float G0[32], G1[32];
#pragma unroll
    for (int k = 0; k < 32; k++) {
        G0[k] = row[k * 64 + lane];
        G1[k] = row[k * 64 + 32 + lane];
    }
    float u0 = row[2112 + lane], u1 = row[2144 + lane];
    const float* rbase = g_r + (size_t)layer * EE * KH;
    for (int p = beg; p < end; p++) {
        int e = g_csr[p];
        int d = dst[e];
        float rk = rbase[e * KH + lane];
        float a0 = u0, a1 = u1;
#pragma unroll
        for (int k = 0; k < 32; k++) {
            float rv = __shfl_sync(0xffffffffu, rk, k);
            a0 += rv * G0[k];
            a1 += rv * G1[k];
        }
        atomicAdd(&g_agg[d * H + lane], a0);
        atomicAdd(&g_agg[d * H + 32 + lane], a1);
    }
}

// ===================== norm passes =====================
__global__ __launch_bounds__(256) void k_pass1(const float* __restrict__ rb) {
    __shared__ float rs[256], rs2[256];
    int tid = threadIdx.x;
    int o = tid & 63, g = tid >> 6;
    float s = 0.0f, s2 = 0.0f;
    int nbase = blockIdx.x * 64;
    for (int j = 0; j < 16; j++) {
        int n = nbase + j * 4 + g;
        if (n < NN) {
            int idx = n * H + o;
            float v = g_agg[idx] * g_invdeg[n] + g_GB[(size_t)n * NB + 2048 + o] + rb[o];
            g_hpre[idx] = v;
            s += v;
            s2 += v * v;
        }
    }
    rs[tid] = s;
    rs2[tid] = s2;
    __syncthreads();
    if (tid < 64) {
        float t = rs[tid] + rs[tid + 64] + rs[tid + 128] + rs[tid + 192];
        float t2 = rs2[tid] + rs2[tid + 64] + rs2[tid + 128] + rs2[tid + 192];
        atomicAdd(&g_colsum[tid], t);
        atomicAdd(&g_colsumsq[tid], t2);
    }
}
__global__ void k_finalize(const float* __restrict__ gw, const float* __restrict__ gb,
                           const float* __restrict__ gms) {
    int o = threadIdx.x;
    float mean = g_colsum[o] * (1.0f / NN);
    float ex2 = g_colsumsq[o] * (1.0f / NN);
    float ms = gms[o];
    float var = ex2 - (2.0f * ms - ms * ms) * mean * mean;
    float a = gw[o] * rsqrtf(var + GEPS);
    g_ga[o] = a;
    g_gc[o] = gb[o] - a * ms * mean;
}
// l==0: leaky-relu, write next-layer g_A (hi|hi|lo), re-zero agg/colsums. l==1: write out.
__global__ void k_pass2(int l, float* __restrict__ out) {
    int idx = blockIdx.x * blockDim.x + threadIdx.x;
    if (idx >= NN * H) return;
    int n = idx >> 6, o = idx & 63;
    float v = g_ga[o] * g_hpre[idx] + g_gc[o];
    if (l == 0) {
        v = (v > 0.0f) ? v : 0.2f * v;
        __nv_bfloat16 hi = __float2bfloat16(v);
        __nv_bfloat16 lo = __float2bfloat16(v - __bfloat162float(hi));
        g_A[n * KB + o] = hi;
        g_A[n * KB + 64 + o] = hi;
        g_A[n * KB + 128 + o] = lo;
        g_agg[idx] = 0.0f;
        if (idx < H) g_colsum[idx] = 0.0f;
        else if (idx < 2 * H) g_colsumsq[idx - H] = 0.0f;
    } else {
        out[idx] = v;
    }
}

// ===================== launch =====================
extern "C" void kernel_launch(void* const* d_in, const int* in_sizes, int n_in,
                              void* d_out, int out_size) {
    const float* x      = (const float*)d_in[0];
    const int*   ei     = (const int*)d_in[1];
    const float* ea     = (const float*)d_in[2];
    const float* proj_w = (const float*)d_in[3];
    const float* proj_b = (const float*)d_in[4];
    const float* enn_w1 = (const float*)d_in[5];
    const float* enn_b1 = (const float*)d_in[6];
    const float* enn_w2 = (const float*)d_in[7];
    const float* enn_b2 = (const float*)d_in[8];
    const float* root_w = (const float*)d_in[9];
    const float* root_b = (const float*)d_in[10];
    const float* gn_w   = (const float*)d_in[11];
    const float* gn_b   = (const float*)d_in[12];
    const float* gn_ms  = (const float*)d_in[13];
    const int* src = ei;
    const int* dst = ei + EE;

    // order chosen so launch #4 (= ncu capture slot) is k_gemm layer 0
    k_proj<<<(MPAD * H + 255) / 256, 256>>>(x, proj_w, proj_b);
    k_Bprep<<<(2 * NB * KB + 255) / 256, 256>>>(enn_w2, root_w, enn_b2);
    k_zero<<<(NN + 255) / 256, 256>>>();
    k_gemm<<<dim3(79, 17), 256>>>(0);
    k_count<<<(EE + 255) / 256, 256>>>(src, dst);
    k_scan<<<1, 1024>>>();
    k_fill<<<(EE + 255) / 256, 256>>>(src);
    k_mlp<<<(2 * EE * KH + 255) / 256, 256>>>(ea, enn_w1, enn_b1);
    k_msg<<<(NN + 7) / 8, 256>>>(dst, 0);
    k_pass1<<<(NN + 63) / 64, 256>>>(root_b);
    k_finalize<<<1, 64>>>(gn_w, gn_b, gn_ms);
    k_pass2<<<(NN * H + 255) / 256, 256>>>(0, (float*)d_out);
    k_gemm<<<dim3(79, 17), 256>>>(1);
    k_msg<<<(NN + 7) / 8, 256>>>(dst, 1);
    k_pass1<<<(NN + 63) / 64, 256>>>(root_b + H);
    k_finalize<<<1, 64>>>(gn_w + H, gn_b + H, gn_ms + H);
    k_pass2<<<(NN * H + 255) / 256, 256>>>(1, (float*)d_out);
}

// round 5
// speedup vs baseline: 1.5519x; 1.0853x over previous
#include <cuda_runtime.h>
#include <cuda_bf16.h>
#include <cstdint>

#define NN 10000
#define MPAD 10240           // 40 * 256
#define EE 50000
#define IND 8
#define H 64
#define KH 32
#define KB 192               // stacked K: [h_hi | h_hi | h_lo]
#define NB 2176              // 2048 (G) + 64 (root_w base) + 64 (B2 u-term)
#define GEPS 1e-5f

// ===================== device scratch =====================
__device__ float g_hpre[NN * H];
__device__ float g_agg[NN * H];
__device__ float g_r[2 * EE * KH];
__device__ __nv_bfloat16 g_A[MPAD * KB];            // [h_hi | h_hi | h_lo]
__device__ __nv_bfloat16 g_B[2 * NB * KB];          // per-layer [N-row][K] bf16
__device__ float g_GB[(size_t)MPAD * NB];           // GEMM output: G | base | u
__device__ int g_sdeg[NN], g_ddeg[NN];
__device__ int g_soff[NN], g_cursor[NN], g_csr[EE];
__device__ int g_total;
__device__ float g_invdeg[NN];
__device__ float g_colsum[H], g_colsumsq[H];
__device__ float g_ga[H], g_gc[H];

__device__ __forceinline__ uint32_t smem_u32(const void* p) {
    uint32_t a;
    asm("{ .reg .u64 t; cvta.to.shared.u64 t, %1; cvt.u32.u64 %0, t; }" : "=r"(a) : "l"(p));
    return a;
}

// ===================== setup kernels =====================
__global__ void k_zero() {
    int i = blockIdx.x * blockDim.x + threadIdx.x;
    if (i < NN) { g_sdeg[i] = 0; g_ddeg[i] = 0; }
    if (i < H) { g_colsum[i] = 0.0f; g_colsumsq[i] = 0.0f; }
    if (i == 0) g_total = 0;
}
__global__ void k_count(const int* __restrict__ src, const int* __restrict__ dst) {
    int i = blockIdx.x * blockDim.x + threadIdx.x;
    if (i < EE) { atomicAdd(&g_sdeg[src[i]], 1); atomicAdd(&g_ddeg[dst[i]], 1); }
}
// order-free CSR offsets (bucket contents identical regardless of assignment order)
__global__ void k_offsets() {
    int i = blockIdx.x * blockDim.x + threadIdx.x;
    if (i >= NN) return;
    int d = g_sdeg[i];
    int pos = (d > 0) ? atomicAdd(&g_total, d) : 0;
    g_soff[i] = pos;
    g_cursor[i] = pos;
    g_invdeg[i] = 1.0f / fmaxf((float)g_ddeg[i], 1.0f);
}
__global__ void k_fill(const int* __restrict__ src) {
    int e = blockIdx.x * blockDim.x + threadIdx.x;
    if (e < EE) {
        int pos = atomicAdd(&g_cursor[src[e]], 1);
        g_csr[pos] = e;
    }
}
// h = x@proj_w+proj_b, split into g_A [hi|hi|lo]; zero agg; pad rows zeroed
__global__ void k_proj(const float* __restrict__ x, const float* __restrict__ w,
                       const float* __restrict__ b) {
    int idx = blockIdx.x * blockDim.x + threadIdx.x;
    if (idx >= MPAD * H) return;
    int n = idx >> 6, o = idx & 63;
    float v = 0.0f;
    if (n < NN) {
        v = b[o];
#pragma unroll
        for (int i = 0; i < IND; i++) v += x[n * IND + i] * w[i * H + o];
        g_agg[idx] = 0.0f;
    }
    __nv_bfloat16 hi = __float2bfloat16(v);
    __nv_bfloat16 lo = __float2bfloat16(v - __bfloat162float(hi));
    g_A[n * KB + o] = hi;
    g_A[n * KB + 64 + o] = hi;
    g_A[n * KB + 128 + o] = lo;
}
// r = relu(edge_attr @ W1 + b1) for BOTH layers
__global__ void k_mlp(const float* __restrict__ ea, const float* __restrict__ w1,
                      const float* __restrict__ b1) {
    int idx = blockIdx.x * blockDim.x + threadIdx.x;
    if (idx >= 2 * EE * KH) return;
    int l = idx / (EE * KH);
    int rem = idx - l * (EE * KH);
    int e = rem >> 5, k = rem & 31;
    float acc = b1[l * KH + k];
#pragma unroll
    for (int d = 0; d < 4; d++) acc += ea[e * 4 + d] * w1[l * 128 + d * KH + k];
    g_r[idx] = fmaxf(acc, 0.0f);
}
// Build B [l][c][k]: K-blocks {hi(W), lo(W), hi(W)}
__global__ void k_Bprep(const float* __restrict__ w2, const float* __restrict__ rw,
                        const float* __restrict__ b2) {
    int idx = blockIdx.x * blockDim.x + threadIdx.x;
    if (idx >= 2 * NB * KB) return;
    int l = idx / (NB * KB);
    int rem = idx - l * (NB * KB);
    int c = rem / KB, k = rem - c * KB;
    int blk = k >> 6, i = k & 63;
    float S;
    if (c < 2048) S = w2[l * 131072 + (c >> 6) * 4096 + i * 64 + (c & 63)];
    else if (c < 2112) S = rw[l * 4096 + i * 64 + (c - 2048)];
    else S = b2[l * 4096 + i * 64 + (c - 2112)];
    __nv_bfloat16 hi = __float2bfloat16(S);
    __nv_bfloat16 v = (blk == 1) ? __float2bfloat16(S - __bfloat162float(hi)) : hi;
    g_B[idx] = v;
}

// ===================== warp-MMA GEMM: 256x128 block, 64x64 warp tiles =====================
__device__ __forceinline__ void mma_bf16(float* c, const uint32_t* a, const uint32_t* b) {
    asm volatile(
        "mma.sync.aligned.m16n8k16.row.col.f32.bf16.bf16.f32 "
        "{%0,%1,%2,%3}, {%4,%5,%6,%7}, {%8,%9}, {%0,%1,%2,%3};"
        : "+f"(c[0]), "+f"(c[1]), "+f"(c[2]), "+f"(c[3])
        : "r"(a[0]), "r"(a[1]), "r"(a[2]), "r"(a[3]), "r"(b[0]), "r"(b[1]));
}
__device__ __forceinline__ void cp16(uint32_t sdst, const void* gsrc) {
    asm volatile("cp.async.ca.shared.global [%0], [%1], 16;" :: "r"(sdst), "l"(gsrc));
}
#define CPCOMMIT() asm volatile("cp.async.commit_group;" ::: "memory")
#define CPWAIT1() asm volatile("cp.async.wait_group 1;" ::: "memory")

#define CH 16      // K elems per chunk -> 12 chunks
#define SST 24     // smem row stride in bf16 elems (48B): banks (12g+tc)%32 all distinct
#define STG (384 * SST)   // elems per stage (A rows 0..255, B rows 256..383)

__global__ __launch_bounds__(256, 1) void k_gemm(int layer) {
    __shared__ __nv_bfloat16 sm[2][STG];   // 2*384*24*2 = 36864 B
    int tid = threadIdx.x;
    int lane = tid & 31, w = tid >> 5;
    int wm = w >> 1, wn = w & 1;           // 4(M) x 2(N) warps, 64x64 each
    int g = lane >> 2, tc = lane & 3;
    int n0 = blockIdx.x * 256, nb0 = blockIdx.y * 128;
    const __nv_bfloat16* Bg = g_B + (size_t)layer * NB * KB;

    // copy slots: 3 per thread; slot -> (row, 16B-half)
    const __nv_bfloat16* gsrc[3];
    uint32_t sdst[3];
#pragma unroll
    for (int k = 0; k < 3; k++) {
        int slot = tid + k * 256;
        int row = slot >> 1, h = (slot & 1) * 8;   // h in elems
        gsrc[k] = (row < 256) ? g_A + (size_t)(n0 + row) * KB + h
                              : Bg + (size_t)(nb0 + row - 256) * KB + h;
        sdst[k] = smem_u32(&sm[0][row * SST + h]);
    }
#define ISSUE(c, st) do {                                               \
        uint32_t o = (uint32_t)(st) * (STG * 2);                        \
        cp16(sdst[0] + o, gsrc[0] + (c) * CH);                          \
        cp16(sdst[1] + o, gsrc[1] + (c) * CH);                          \
        cp16(sdst[2] + o, gsrc[2] + (c) * CH);                          \
    } while (0)

    ISSUE(0, 0); CPCOMMIT();
    ISSUE(1, 1); CPCOMMIT();

    float acc[4][8][4] = {};
#pragma unroll
    for (int c = 0; c < 12; c++) {
        CPWAIT1();
        __syncthreads();
        const __nv_bfloat16* base = sm[c & 1];
        uint32_t af[4][4], bf[8][2];
#pragma unroll
        for (int mi = 0; mi < 4; mi++) {
            int r0 = wm * 64 + mi * 16 + g;
            const __nv_bfloat16* pa = base + tc * 2;
            af[mi][0] = *(const uint32_t*)(pa + r0 * SST);
            af[mi][1] = *(const uint32_t*)(pa + (r0 + 8) * SST);
            af[mi][2] = *(const uint32_t*)(pa + r0 * SST + 8);
            af[mi][3] = *(const uint32_t*)(pa + (r0 + 8) * SST + 8);
        }
#pragma unroll
        for (int ni = 0; ni < 8; ni++) {
            const __nv_bfloat16* pb = base + (256 + wn * 64 + ni * 8 + g) * SST + tc * 2;
            bf[ni][0] = *(const uint32_t*)pb;
            bf[ni][1] = *(const uint32_t*)(pb + 8);
        }
#pragma unroll
        for (int mi = 0; mi < 4; mi++)
#pragma unroll
            for (int ni = 0; ni < 8; ni++)
                mma_bf16(acc[mi][ni], af[mi], bf[ni]);
        __syncthreads();
        if (c + 2 < 12) ISSUE(c + 2, c & 1);
        CPCOMMIT();
    }
    // epilogue: fragment-mapped direct stores
#pragma unroll
    for (int mi = 0; mi < 4; mi++) {
        int row0 = n0 + wm * 64 + mi * 16 + g;
#pragma unroll
        for (int ni = 0; ni < 8; ni++) {
            int col = nb0 + wn * 64 + ni * 8 + tc * 2;
            *(float2*)(g_GB + (size_t)row0 * NB + col) =
                make_float2(acc[mi][ni][0], acc[mi][ni][1]);
            *(float2*)(g_GB + (size_t)(row0 + 8) * NB + col) =
                make_float2(acc[mi][ni][2], acc[mi][ni][3]);
        }
    }
#undef ISSUE
}

// ===================== message pass: warp per src node, G row in registers =====================
__global__ __launch_bounds__(256) void k_msg(const int* __restrict__ dst, int layer) {
    int w = blockIdx.x * 8 + (threadIdx.x >> 5);
    int lane = threadIdx.x & 31;
    if (w >= NN) return;
    int cnt = g_sdeg[w];
    if (cnt == 0) return;
    int beg = g_soff[w];
    const float* row = g_GB + (size_t)w * NB;
    float G0[32], G1[32];
#pragma unroll
    for (int k = 0; k < 32; k++) {
        G0[k] = row[k * 64 + lane];
        G1[k] = row[k * 64 + 32 + lane];
    }
    float u0 = row[2112 + lane], u1 = row[2144 + lane];
    const float* rbase = g_r + (size_t)layer * EE * KH;
    for (int p = beg; p < beg + cnt; p++) {
        int e = g_csr[p];
        int d = dst[e];
        float rk = rbase[e * KH + lane];
        float a0 = u0, a1 = u1;
#pragma unroll
        for (int k = 0; k < 32; k++) {
            float rv = __shfl_sync(0xffffffffu, rk, k);
            a0 += rv * G0[k];
            a1 += rv * G1[k];
        }
        atomicAdd(&g_agg[d * H + lane], a0);
        atomicAdd(&g_agg[d * H + 32 + lane], a1);
    }
}

// ===================== norm passes =====================
__global__ __launch_bounds__(256) void k_pass1(const float* __restrict__ rb) {
    __shared__ float rs[256], rs2[256];
    int tid = threadIdx.x;
    int o = tid & 63, g = tid >> 6;
    float s = 0.0f, s2 = 0.0f;
    int nbase = blockIdx.x * 64;
    for (int j = 0; j < 16; j++) {
        int n = nbase + j * 4 + g;
        if (n < NN) {
            int idx = n * H + o;
            float v = g_agg[idx] * g_invdeg[n] + g_GB[(size_t)n * NB + 2048 + o] + rb[o];
            g_hpre[idx] = v;
            s += v;
            s2 += v * v;
        }
    }
    rs[tid] = s;
    rs2[tid] = s2;
    __syncthreads();
    if (tid < 64) {
        float t = rs[tid] + rs[tid + 64] + rs[tid + 128] + rs[tid + 192];
        float t2 = rs2[tid] + rs2[tid + 64] + rs2[tid + 128] + rs2[tid + 192];
        atomicAdd(&g_colsum[tid], t);
        atomicAdd(&g_colsumsq[tid], t2);
    }
}
__global__ void k_finalize(const float* __restrict__ gw, const float* __restrict__ gb,
                           const float* __restrict__ gms) {
    int o = threadIdx.x;
    float mean = g_colsum[o] * (1.0f / NN);
    float ex2 = g_colsumsq[o] * (1.0f / NN);
    float ms = gms[o];
    float var = ex2 - (2.0f * ms - ms * ms) * mean * mean;
    float a = gw[o] * rsqrtf(var + GEPS);
    g_ga[o] = a;
    g_gc[o] = gb[o] - a * ms * mean;
}
// l==0: leaky-relu, write next-layer g_A (hi|hi|lo), re-zero agg/colsums. l==1: write out.
__global__ void k_pass2(int l, float* __restrict__ out) {
    int idx = blockIdx.x * blockDim.x + threadIdx.x;
    if (idx >= NN * H) return;
    int n = idx >> 6, o = idx & 63;
    float v = g_ga[o] * g_hpre[idx] + g_gc[o];
    if (l == 0) {
        v = (v > 0.0f) ? v : 0.2f * v;
        __nv_bfloat16 hi = __float2bfloat16(v);
        __nv_bfloat16 lo = __float2bfloat16(v - __bfloat162float(hi));
        g_A[n * KB + o] = hi;
        g_A[n * KB + 64 + o] = hi;
        g_A[n * KB + 128 + o] = lo;
        g_agg[idx] = 0.0f;
        if (idx < H) g_colsum[idx] = 0.0f;
        else if (idx < 2 * H) g_colsumsq[idx - H] = 0.0f;
    } else {
        out[idx] = v;
    }
}

// ===================== launch =====================
extern "C" void kernel_launch(void* const* d_in, const int* in_sizes, int n_in,
                              void* d_out, int out_size) {
    const float* x      = (const float*)d_in[0];
    const int*   ei     = (const int*)d_in[1];
    const float* ea     = (const float*)d_in[2];
    const float* proj_w = (const float*)d_in[3];
    const float* proj_b = (const float*)d_in[4];
    const float* enn_w1 = (const float*)d_in[5];
    const float* enn_b1 = (const float*)d_in[6];
    const float* enn_w2 = (const float*)d_in[7];
    const float* enn_b2 = (const float*)d_in[8];
    const float* root_w = (const float*)d_in[9];
    const float* root_b = (const float*)d_in[10];
    const float* gn_w   = (const float*)d_in[11];
    const float* gn_b   = (const float*)d_in[12];
    const float* gn_ms  = (const float*)d_in[13];
    const int* src = ei;
    const int* dst = ei + EE;

    // order chosen so launch #4 (= ncu capture slot) is k_gemm layer 0
    k_proj<<<(MPAD * H + 255) / 256, 256>>>(x, proj_w, proj_b);
    k_Bprep<<<(2 * NB * KB + 255) / 256, 256>>>(enn_w2, root_w, enn_b2);
    k_zero<<<(NN + 255) / 256, 256>>>();
    k_gemm<<<dim3(40, 17), 256>>>(0);
    k_count<<<(EE + 255) / 256, 256>>>(src, dst);
    k_offsets<<<(NN + 255) / 256, 256>>>();
    k_fill<<<(EE + 255) / 256, 256>>>(src);
    k_mlp<<<(2 * EE * KH + 255) / 256, 256>>>(ea, enn_w1, enn_b1);
    k_msg<<<(NN + 7) / 8, 256>>>(dst, 0);
    k_pass1<<<(NN + 63) / 64, 256>>>(root_b);
    k_finalize<<<1, 64>>>(gn_w, gn_b, gn_ms);
    k_pass2<<<(NN * H + 255) / 256, 256>>>(0, (float*)d_out);
    k_gemm<<<dim3(40, 17), 256>>>(1);
    k_msg<<<(NN + 7) / 8, 256>>>(dst, 1);
    k_pass1<<<(NN + 63) / 64, 256>>>(root_b + H);
    k_finalize<<<1, 64>>>(gn_w + H, gn_b + H, gn_ms + H);
    k_pass2<<<(NN * H + 255) / 256, 256>>>(1, (float*)d_out);
}

// round 6
// speedup vs baseline: 1.6440x; 1.0594x over previous
#include <cuda_runtime.h>
#include <cuda_bf16.h>
#include <cstdint>

#define NN 10000
#define MPAD 10240           // 40 * 256
#define EE 50000
#define IND 8
#define H 64
#define KH 32
#define KB 192               // stacked K: [h_hi | h_hi | h_lo]
#define NB 2176              // 2048 (G) + 64 (root_w base) + 64 (B2 u-term)
#define GEPS 1e-5f

// ===================== device scratch =====================
__device__ float g_hpre[NN * H];
__device__ float g_agg[NN * H];
__device__ float g_r[2 * EE * KH];
__device__ __nv_bfloat16 g_A[MPAD * KB];            // [h_hi | h_hi | h_lo]
__device__ __nv_bfloat16 g_B[2 * NB * KB];          // per-layer [N-row][K] bf16
__device__ float g_GB[(size_t)MPAD * NB];           // GEMM output: G | base | u
__device__ int g_sdeg[NN], g_ddeg[NN];
__device__ int g_soff[NN], g_cursor[NN], g_csr[EE];
__device__ int g_total;
__device__ float g_invdeg[NN];
__device__ float g_colsum[2][H], g_colsumsq[2][H];

__device__ __forceinline__ uint32_t smem_u32(const void* p) {
    uint32_t a;
    asm("{ .reg .u64 t; cvta.to.shared.u64 t, %1; cvt.u32.u64 %0, t; }" : "=r"(a) : "l"(p));
    return a;
}

// ===================== setup kernels =====================
// h = x@proj_w+proj_b split into g_A [hi|hi|lo]; zero agg + counters (fused k_zero)
__global__ void k_proj(const float* __restrict__ x, const float* __restrict__ w,
                       const float* __restrict__ b) {
    int idx = blockIdx.x * blockDim.x + threadIdx.x;
    if (idx >= MPAD * H) return;
    if (idx < NN) { g_sdeg[idx] = 0; g_ddeg[idx] = 0; }
    if (idx < H) {
        g_colsum[0][idx] = 0.0f; g_colsumsq[0][idx] = 0.0f;
        g_colsum[1][idx] = 0.0f; g_colsumsq[1][idx] = 0.0f;
    }
    if (idx == 0) g_total = 0;
    int n = idx >> 6, o = idx & 63;
    float v = 0.0f;
    if (n < NN) {
        v = b[o];
#pragma unroll
        for (int i = 0; i < IND; i++) v += x[n * IND + i] * w[i * H + o];
        g_agg[idx] = 0.0f;
    }
    __nv_bfloat16 hi = __float2bfloat16(v);
    __nv_bfloat16 lo = __float2bfloat16(v - __bfloat162float(hi));
    g_A[n * KB + o] = hi;
    g_A[n * KB + 64 + o] = hi;
    g_A[n * KB + 128 + o] = lo;
}
__global__ void k_count(const int* __restrict__ src, const int* __restrict__ dst) {
    int i = blockIdx.x * blockDim.x + threadIdx.x;
    if (i < EE) { atomicAdd(&g_sdeg[src[i]], 1); atomicAdd(&g_ddeg[dst[i]], 1); }
}
// order-free CSR offsets (bucket contents identical regardless of assignment order)
__global__ void k_offsets() {
    int i = blockIdx.x * blockDim.x + threadIdx.x;
    if (i >= NN) return;
    int d = g_sdeg[i];
    int pos = (d > 0) ? atomicAdd(&g_total, d) : 0;
    g_soff[i] = pos;
    g_cursor[i] = pos;
    g_invdeg[i] = 1.0f / fmaxf((float)g_ddeg[i], 1.0f);
}
__global__ void k_fill(const int* __restrict__ src) {
    int e = blockIdx.x * blockDim.x + threadIdx.x;
    if (e < EE) {
        int pos = atomicAdd(&g_cursor[src[e]], 1);
        g_csr[pos] = e;
    }
}
// merged: edge-MLP (both layers) + B matrix build (both layers)
#define MLPN (2 * EE * KH)
__global__ void k_prep(const float* __restrict__ ea, const float* __restrict__ w1,
                       const float* __restrict__ b1, const float* __restrict__ w2,
                       const float* __restrict__ rw, const float* __restrict__ b2) {
    int idx = blockIdx.x * blockDim.x + threadIdx.x;
    if (idx < MLPN) {
        int l = idx / (EE * KH);
        int rem = idx - l * (EE * KH);
        int e = rem >> 5, k = rem & 31;
        float acc = b1[l * KH + k];
#pragma unroll
        for (int d = 0; d < 4; d++) acc += ea[e * 4 + d] * w1[l * 128 + d * KH + k];
        g_r[idx] = fmaxf(acc, 0.0f);
        return;
    }
    int t = idx - MLPN;
    if (t >= 2 * NB * KB) return;
    int l = t / (NB * KB);
    int rem = t - l * (NB * KB);
    int c = rem / KB, k = rem - c * KB;
    int blk = k >> 6, i = k & 63;
    float S;
    if (c < 2048) S = w2[l * 131072 + (c >> 6) * 4096 + i * 64 + (c & 63)];
    else if (c < 2112) S = rw[l * 4096 + i * 64 + (c - 2048)];
    else S = b2[l * 4096 + i * 64 + (c - 2112)];
    __nv_bfloat16 hi = __float2bfloat16(S);
    __nv_bfloat16 v = (blk == 1) ? __float2bfloat16(S - __bfloat162float(hi)) : hi;
    g_B[t] = v;
}

// ===================== warp-MMA GEMM: 256x128 block, 64x64 warp tiles, ldmatrix =====================
__device__ __forceinline__ void mma_bf16(float* c, const uint32_t* a, const uint32_t* b) {
    asm volatile(
        "mma.sync.aligned.m16n8k16.row.col.f32.bf16.bf16.f32 "
        "{%0,%1,%2,%3}, {%4,%5,%6,%7}, {%8,%9}, {%0,%1,%2,%3};"
        : "+f"(c[0]), "+f"(c[1]), "+f"(c[2]), "+f"(c[3])
        : "r"(a[0]), "r"(a[1]), "r"(a[2]), "r"(a[3]), "r"(b[0]), "r"(b[1]));
}
__device__ __forceinline__ void ldmx4(uint32_t* r, uint32_t addr) {
    asm volatile("ldmatrix.sync.aligned.m8n8.x4.shared.b16 {%0,%1,%2,%3}, [%4];"
                 : "=r"(r[0]), "=r"(r[1]), "=r"(r[2]), "=r"(r[3]) : "r"(addr));
}
__device__ __forceinline__ void cp16(uint32_t sdst, const void* gsrc) {
    asm volatile("cp.async.ca.shared.global [%0], [%1], 16;" :: "r"(sdst), "l"(gsrc));
}
#define CPCOMMIT() asm volatile("cp.async.commit_group;" ::: "memory")
#define CPWAIT1() asm volatile("cp.async.wait_group 1;" ::: "memory")

#define CH 16      // K elems per chunk -> 12 chunks
#define SST 24     // smem row stride in bf16 elems (48B): ldmatrix phase banks 12r%32 distinct
#define STG (384 * SST)   // elems per stage (A rows 0..255, B rows 256..383)

__global__ __launch_bounds__(256, 1) void k_gemm(int layer) {
    __shared__ __nv_bfloat16 sm[2][STG];   // 36864 B
    int tid = threadIdx.x;
    int lane = tid & 31, w = tid >> 5;
    int wm = w >> 1, wn = w & 1;           // 4(M) x 2(N) warps, 64x64 each
    int g = lane >> 2, tc = lane & 3;
    int n0 = blockIdx.x * 256, nb0 = blockIdx.y * 128;
    const __nv_bfloat16* Bg = g_B + (size_t)layer * NB * KB;

    // cp.async slots: 3 per thread
    const __nv_bfloat16* gsrc[3];
    uint32_t sdst[3];
#pragma unroll
    for (int k = 0; k < 3; k++) {
        int slot = tid + k * 256;
        int row = slot >> 1, h = (slot & 1) * 8;
        gsrc[k] = (row < 256) ? g_A + (size_t)(n0 + row) * KB + h
                              : Bg + (size_t)(nb0 + row - 256) * KB + h;
        sdst[k] = smem_u32(&sm[0][row * SST + h]);
    }
#define ISSUE(c, st) do {                                               \
        uint32_t o = (uint32_t)(st) * (STG * 2);                        \
        cp16(sdst[0] + o, gsrc[0] + (c) * CH);                          \
        cp16(sdst[1] + o, gsrc[1] + (c) * CH);                          \
        cp16(sdst[2] + o, gsrc[2] + (c) * CH);                          \
    } while (0)

    // ldmatrix addresses (per stage): A tiles a0..a3, B tiles (n,k) quad
    int arow = (lane & 7) + ((lane >> 3) & 1) * 8;
    int acol = ((lane >> 4) & 1) * 8;
    int brow = (lane & 7) + ((lane >> 4) & 1) * 8;
    int bcol = ((lane >> 3) & 1) * 8;
    uint32_t aAddr[2][4], bAddr[2][4];
#pragma unroll
    for (int st = 0; st < 2; st++) {
#pragma unroll
        for (int mi = 0; mi < 4; mi++)
            aAddr[st][mi] = smem_u32(&sm[st][(wm * 64 + mi * 16 + arow) * SST + acol]);
#pragma unroll
        for (int p = 0; p < 4; p++)
            bAddr[st][p] = smem_u32(&sm[st][(256 + wn * 64 + p * 16 + brow) * SST + bcol]);
    }

    ISSUE(0, 0); CPCOMMIT();
    ISSUE(1, 1); CPCOMMIT();

    float acc[4][8][4] = {};
#pragma unroll
    for (int c = 0; c < 12; c++) {
        CPWAIT1();
        __syncthreads();
        int st = c & 1;
        uint32_t af[4][4], bq[4][4];
#pragma unroll
        for (int mi = 0; mi < 4; mi++) ldmx4(af[mi], aAddr[st][mi]);
#pragma unroll
        for (int p = 0; p < 4; p++) ldmx4(bq[p], bAddr[st][p]);
#pragma unroll
        for (int mi = 0; mi < 4; mi++)
#pragma unroll
            for (int ni = 0; ni < 8; ni++)
                mma_bf16(acc[mi][ni], af[mi], &bq[ni >> 1][(ni & 1) * 2]);
        __syncthreads();
        if (c + 2 < 12) ISSUE(c + 2, st);
        CPCOMMIT();
    }
    // epilogue: fragment-mapped direct stores
#pragma unroll
    for (int mi = 0; mi < 4; mi++) {
        int row0 = n0 + wm * 64 + mi * 16 + g;
#pragma unroll
        for (int ni = 0; ni < 8; ni++) {
            int col = nb0 + wn * 64 + ni * 8 + tc * 2;
            *(float2*)(g_GB + (size_t)row0 * NB + col) =
                make_float2(acc[mi][ni][0], acc[mi][ni][1]);
            *(float2*)(g_GB + (size_t)(row0 + 8) * NB + col) =
                make_float2(acc[mi][ni][2], acc[mi][ni][3]);
        }
    }
#undef ISSUE
}

// ===================== message pass: warp per src node, G row in registers =====================
__global__ __launch_bounds__(256) void k_msg(const int* __restrict__ dst, int layer) {
    int w = blockIdx.x * 8 + (threadIdx.x >> 5);
    int lane = threadIdx.x & 31;
    if (w >= NN) return;
    int cnt = g_sdeg[w];
    if (cnt == 0) return;
    int beg = g_soff[w];
    const float* row = g_GB + (size_t)w * NB;
    float G0[32], G1[32];
#pragma unroll
    for (int k = 0; k < 32; k++) {
        G0[k] = row[k * 64 + lane];
        G1[k] = row[k * 64 + 32 + lane];
    }
    float u0 = row[2112 + lane], u1 = row[2144 + lane];
    const float* rbase = g_r + (size_t)layer * EE * KH;
    for (int p = beg; p < beg + cnt; p++) {
        int e = g_csr[p];
        int d = dst[e];
        float rk = rbase[e * KH + lane];
        float a0 = u0, a1 = u1;
#pragma unroll
        for (int k = 0; k < 32; k++) {
            float rv = __shfl_sync(0xffffffffu, rk, k);
            a0 += rv * G0[k];
            a1 += rv * G1[k];
        }
        atomicAdd(&g_agg[d * H + lane], a0);
        atomicAdd(&g_agg[d * H + 32 + lane], a1);
    }
}

// ===================== norm passes =====================
__global__ __launch_bounds__(256) void k_pass1(const float* __restrict__ rb, int l) {
    __shared__ float rs[256], rs2[256];
    int tid = threadIdx.x;
    int o = tid & 63, g = tid >> 6;
    float s = 0.0f, s2 = 0.0f;
    int nbase = blockIdx.x * 64;
    for (int j = 0; j < 16; j++) {
        int n = nbase + j * 4 + g;
        if (n < NN) {
            int idx = n * H + o;
            float v = g_agg[idx] * g_invdeg[n] + g_GB[(size_t)n * NB + 2048 + o] + rb[o];
            g_hpre[idx] = v;
            s += v;
            s2 += v * v;
        }
    }
    rs[tid] = s;
    rs2[tid] = s2;
    __syncthreads();
    if (tid < 64) {
        float t = rs[tid] + rs[tid + 64] + rs[tid + 128] + rs[tid + 192];
        float t2 = rs2[tid] + rs2[tid + 64] + rs2[tid + 128] + rs2[tid + 192];
        atomicAdd(&g_colsum[l][tid], t);
        atomicAdd(&g_colsumsq[l][tid], t2);
    }
}
// finalize folded in: each thread recomputes norm scalars from per-layer colsums
__global__ void k_pass2(int l, float* __restrict__ out, const float* __restrict__ gw,
                        const float* __restrict__ gb, const float* __restrict__ gms) {
    int idx = blockIdx.x * blockDim.x + threadIdx.x;
    if (idx >= NN * H) return;
    int n = idx >> 6, o = idx & 63;
    float mean = g_colsum[l][o] * (1.0f / NN);
    float ex2 = g_colsumsq[l][o] * (1.0f / NN);
    float ms = gms[o];
    float var = ex2 - (2.0f * ms - ms * ms) * mean * mean;
    float a = gw[o] * rsqrtf(var + GEPS);
    float cc = gb[o] - a * ms * mean;
    float v = a * g_hpre[idx] + cc;
    if (l == 0) {
        v = (v > 0.0f) ? v : 0.2f * v;
        __nv_bfloat16 hi = __float2bfloat16(v);
        __nv_bfloat16 lo = __float2bfloat16(v - __bfloat162float(hi));
        g_A[n * KB + o] = hi;
        g_A[n * KB + 64 + o] = hi;
        g_A[n * KB + 128 + o] = lo;
        g_agg[idx] = 0.0f;
    } else {
        out[idx] = v;
    }
}

// ===================== launch =====================
extern "C" void kernel_launch(void* const* d_in, const int* in_sizes, int n_in,
                              void* d_out, int out_size) {
    const float* x      = (const float*)d_in[0];
    const int*   ei     = (const int*)d_in[1];
    const float* ea     = (const float*)d_in[2];
    const float* proj_w = (const float*)d_in[3];
    const float* proj_b = (const float*)d_in[4];
    const float* enn_w1 = (const float*)d_in[5];
    const float* enn_b1 = (const float*)d_in[6];
    const float* enn_w2 = (const float*)d_in[7];
    const float* enn_b2 = (const float*)d_in[8];
    const float* root_w = (const float*)d_in[9];
    const float* root_b = (const float*)d_in[10];
    const float* gn_w   = (const float*)d_in[11];
    const float* gn_b   = (const float*)d_in[12];
    const float* gn_ms  = (const float*)d_in[13];
    const int* src = ei;
    const int* dst = ei + EE;

    // launch #4 (= ncu capture slot) is k_gemm layer 0
    k_proj<<<(MPAD * H + 255) / 256, 256>>>(x, proj_w, proj_b);
    k_prep<<<(MLPN + 2 * NB * KB + 255) / 256, 256>>>(ea, enn_w1, enn_b1,
                                                      enn_w2, root_w, enn_b2);
    k_count<<<(EE + 255) / 256, 256>>>(src, dst);
    k_gemm<<<dim3(40, 17), 256>>>(0);
    k_offsets<<<(NN + 255) / 256, 256>>>();
    k_fill<<<(EE + 255) / 256, 256>>>(src);
    k_msg<<<(NN + 7) / 8, 256>>>(dst, 0);
    k_pass1<<<(NN + 63) / 64, 256>>>(root_b, 0);
    k_pass2<<<(NN * H + 255) / 256, 256>>>(0, (float*)d_out, gn_w, gn_b, gn_ms);
    k_gemm<<<dim3(40, 17), 256>>>(1);
    k_msg<<<(NN + 7) / 8, 256>>>(dst, 1);
    k_pass1<<<(NN + 63) / 64, 256>>>(root_b + H, 1);
    k_pass2<<<(NN * H + 255) / 256, 256>>>(1, (float*)d_out, gn_w + H, gn_b + H, gn_ms + H);
}

// round 8
// speedup vs baseline: 1.6489x; 1.0030x over previous
#include <cuda_runtime.h>
#include <cuda_bf16.h>
#include <cstdint>

#define NN 10000
#define MPAD 10240           // 40 * 256
#define EE 50000
#define IND 8
#define H 64
#define KH 32
#define KB 192               // stacked K: [h_hi | h_hi | h_lo]
#define NB 2176              // 2048 (G) + 64 (root_w base) + 64 (B2 u-term)
#define GEPS 1e-5f

// ===================== device scratch =====================
__device__ float g_hpre[NN * H];
__device__ float g_agg[NN * H];
__device__ float g_r[2 * EE * KH];
__device__ __nv_bfloat16 g_A[MPAD * KB];            // [h_hi | h_hi | h_lo]
__device__ __nv_bfloat16 g_B[2 * NB * KB];          // per-layer [N-row][K] bf16
__device__ float g_GB[(size_t)MPAD * NB];           // GEMM output: G | base | u
__device__ int g_sdeg[NN], g_ddeg[NN];
__device__ int g_soff[NN], g_cursor[NN], g_csr[EE];
__device__ int g_total;
__device__ float g_invdeg[NN];
__device__ float g_colsum[2][H], g_colsumsq[2][H];

__device__ __forceinline__ uint32_t smem_u32(const void* p) {
    uint32_t a;
    asm("{ .reg .u64 t; cvta.to.shared.u64 t, %1; cvt.u32.u64 %0, t; }" : "=r"(a) : "l"(p));
    return a;
}

// ===================== setup kernels =====================
// h = x@proj_w+proj_b split into g_A [hi|hi|lo]; zero agg + counters
__global__ void k_proj(const float* __restrict__ x, const float* __restrict__ w,
                       const float* __restrict__ b) {
    int idx = blockIdx.x * blockDim.x + threadIdx.x;
    if (idx >= MPAD * H) return;
    if (idx < NN) { g_sdeg[idx] = 0; g_ddeg[idx] = 0; }
    if (idx < H) {
        g_colsum[0][idx] = 0.0f; g_colsumsq[0][idx] = 0.0f;
        g_colsum[1][idx] = 0.0f; g_colsumsq[1][idx] = 0.0f;
    }
    if (idx == 0) g_total = 0;
    int n = idx >> 6, o = idx & 63;
    float v = 0.0f;
    if (n < NN) {
        v = b[o];
#pragma unroll
        for (int i = 0; i < IND; i++) v += x[n * IND + i] * w[i * H + o];
        g_agg[idx] = 0.0f;
    }
    __nv_bfloat16 hi = __float2bfloat16(v);
    __nv_bfloat16 lo = __float2bfloat16(v - __bfloat162float(hi));
    g_A[n * KB + o] = hi;
    g_A[n * KB + 64 + o] = hi;
    g_A[n * KB + 128 + o] = lo;
}
__global__ void k_count(const int* __restrict__ src, const int* __restrict__ dst) {
    int i = blockIdx.x * blockDim.x + threadIdx.x;
    if (i < EE) { atomicAdd(&g_sdeg[src[i]], 1); atomicAdd(&g_ddeg[dst[i]], 1); }
}
// order-free CSR offsets
__global__ void k_offsets() {
    int i = blockIdx.x * blockDim.x + threadIdx.x;
    if (i >= NN) return;
    int d = g_sdeg[i];
    int pos = (d > 0) ? atomicAdd(&g_total, d) : 0;
    g_soff[i] = pos;
    g_cursor[i] = pos;
    g_invdeg[i] = 1.0f / fmaxf((float)g_ddeg[i], 1.0f);
}
__global__ void k_fill(const int* __restrict__ src) {
    int e = blockIdx.x * blockDim.x + threadIdx.x;
    if (e < EE) {
        int pos = atomicAdd(&g_cursor[src[e]], 1);
        g_csr[pos] = e;
    }
}
// merged: edge-MLP (both layers) + B matrix build (both layers)
#define MLPN (2 * EE * KH)
__global__ void k_prep(const float* __restrict__ ea, const float* __restrict__ w1,
                       const float* __restrict__ b1, const float* __restrict__ w2,
                       const float* __restrict__ rw, const float* __restrict__ b2) {
    int idx = blockIdx.x * blockDim.x + threadIdx.x;
    if (idx < MLPN) {
        int l = idx / (EE * KH);
        int rem = idx - l * (EE * KH);
        int e = rem >> 5, k = rem & 31;
        float acc = b1[l * KH + k];
#pragma unroll
        for (int d = 0; d < 4; d++) acc += ea[e * 4 + d] * w1[l * 128 + d * KH + k];
        g_r[idx] = fmaxf(acc, 0.0f);
        return;
    }
    int t = idx - MLPN;
    if (t >= 2 * NB * KB) return;
    int l = t / (NB * KB);
    int rem = t - l * (NB * KB);
    int c = rem / KB, k = rem - c * KB;
    int blk = k >> 6, i = k & 63;
    float S;
    if (c < 2048) S = w2[l * 131072 + (c >> 6) * 4096 + i * 64 + (c & 63)];
    else if (c < 2112) S = rw[l * 4096 + i * 64 + (c - 2048)];
    else S = b2[l * 4096 + i * 64 + (c - 2112)];
    __nv_bfloat16 hi = __float2bfloat16(S);
    __nv_bfloat16 v = (blk == 1) ? __float2bfloat16(S - __bfloat162float(hi)) : hi;
    g_B[t] = v;
}

// ===================== warp-MMA GEMM: 256x128 block, 3-stage cp.async (dynamic smem) =====================
__device__ __forceinline__ void mma_bf16(float* c, const uint32_t* a, const uint32_t* b) {
    asm volatile(
        "mma.sync.aligned.m16n8k16.row.col.f32.bf16.bf16.f32 "
        "{%0,%1,%2,%3}, {%4,%5,%6,%7}, {%8,%9}, {%0,%1,%2,%3};"
        : "+f"(c[0]), "+f"(c[1]), "+f"(c[2]), "+f"(c[3])
        : "r"(a[0]), "r"(a[1]), "r"(a[2]), "r"(a[3]), "r"(b[0]), "r"(b[1]));
}
__device__ __forceinline__ void ldmx4(uint32_t* r, uint32_t addr) {
    asm volatile("ldmatrix.sync.aligned.m8n8.x4.shared.b16 {%0,%1,%2,%3}, [%4];"
                 : "=r"(r[0]), "=r"(r[1]), "=r"(r[2]), "=r"(r[3]) : "r"(addr));
}
__device__ __forceinline__ void cp16(uint32_t sdst, const void* gsrc) {
    asm volatile("cp.async.ca.shared.global [%0], [%1], 16;" :: "r"(sdst), "l"(gsrc));
}
#define CPCOMMIT() asm volatile("cp.async.commit_group;" ::: "memory")
#define CPWAIT1() asm volatile("cp.async.wait_group 1;" ::: "memory")

#define CH 16      // K elems per chunk -> 12 chunks
#define SST 24     // row stride (bf16) = 48B (16B-aligned for cp.async); banks (12r+{0,4})%32 distinct
#define STG (384 * SST)           // elems per stage (A rows 0..255, B rows 256..383)
#define GSMEM (3 * STG * 2)       // 55296 bytes dynamic smem

__global__ __launch_bounds__(256, 1) void k_gemm(int layer) {
    extern __shared__ __nv_bfloat16 sm[];   // [3][STG]
    int tid = threadIdx.x;
    int lane = tid & 31, w = tid >> 5;
    int wm = w >> 1, wn = w & 1;           // 4(M) x 2(N) warps, 64x64 each
    int g = lane >> 2, tc = lane & 3;
    int n0 = blockIdx.x * 256, nb0 = blockIdx.y * 128;
    const __nv_bfloat16* Bg = g_B + (size_t)layer * NB * KB;

    // cp.async slots: 3 per thread
    const __nv_bfloat16* gsrc[3];
    uint32_t sdst[3];
#pragma unroll
    for (int k = 0; k < 3; k++) {
        int slot = tid + k * 256;
        int row = slot >> 1, h = (slot & 1) * 8;
        gsrc[k] = (row < 256) ? g_A + (size_t)(n0 + row) * KB + h
                              : Bg + (size_t)(nb0 + row - 256) * KB + h;
        sdst[k] = smem_u32(&sm[row * SST + h]);
    }
#define ISSUE(c, st) do {                                               \
        uint32_t o = (uint32_t)(st) * (STG * 2);                        \
        cp16(sdst[0] + o, gsrc[0] + (c) * CH);                          \
        cp16(sdst[1] + o, gsrc[1] + (c) * CH);                          \
        cp16(sdst[2] + o, gsrc[2] + (c) * CH);                          \
    } while (0)

    // ldmatrix lane->addr mapping (per stage)
    int arow = (lane & 7) + ((lane >> 3) & 1) * 8;
    int acol = ((lane >> 4) & 1) * 8;
    int brow = (lane & 7) + ((lane >> 4) & 1) * 8;
    int bcol = ((lane >> 3) & 1) * 8;
    uint32_t aAddr[3][4], bAddr[3][4];
#pragma unroll
    for (int st = 0; st < 3; st++) {
#pragma unroll
        for (int mi = 0; mi < 4; mi++)
            aAddr[st][mi] = smem_u32(&sm[st * STG + (wm * 64 + mi * 16 + arow) * SST + acol]);
#pragma unroll
        for (int p = 0; p < 4; p++)
            bAddr[st][p] = smem_u32(&sm[st * STG + (256 + wn * 64 + p * 16 + brow) * SST + bcol]);
    }

    ISSUE(0, 0); CPCOMMIT();
    ISSUE(1, 1); CPCOMMIT();

    float acc[4][8][4] = {};
#pragma unroll
    for (int c = 0; c < 12; c++) {
        int st = c % 3;
        CPWAIT1();
        __syncthreads();   // single barrier/chunk: also protects ISSUE below (stage consumed at c-1)
        uint32_t af[4][4], bq[4][4];
#pragma unroll
        for (int mi = 0; mi < 4; mi++) ldmx4(af[mi], aAddr[st][mi]);
#pragma unroll
        for (int p = 0; p < 4; p++) ldmx4(bq[p], bAddr[st][p]);
        if (c + 2 < 12) ISSUE(c + 2, (c + 2) % 3);   // writes stage (c-1)%3: all warps past barrier
        CPCOMMIT();
#pragma unroll
        for (int mi = 0; mi < 4; mi++)
#pragma unroll
            for (int ni = 0; ni < 8; ni++)
                mma_bf16(acc[mi][ni], af[mi], &bq[ni >> 1][(ni & 1) * 2]);
    }
    // epilogue: fragment-mapped direct stores
#pragma unroll
    for (int mi = 0; mi < 4; mi++) {
        int row0 = n0 + wm * 64 + mi * 16 + g;
#pragma unroll
        for (int ni = 0; ni < 8; ni++) {
            int col = nb0 + wn * 64 + ni * 8 + tc * 2;
            *(float2*)(g_GB + (size_t)row0 * NB + col) =
                make_float2(acc[mi][ni][0], acc[mi][ni][1]);
            *(float2*)(g_GB + (size_t)(row0 + 8) * NB + col) =
                make_float2(acc[mi][ni][2], acc[mi][ni][3]);
        }
    }
#undef ISSUE
}

// ===================== message pass: warp per src node, G row in registers =====================
__global__ __launch_bounds__(256) void k_msg(const int* __restrict__ dst, int layer) {
    int w = blockIdx.x * 8 + (threadIdx.x >> 5);
    int lane = threadIdx.x & 31;
    if (w >= NN) return;
    int cnt = g_sdeg[w];
    if (cnt == 0) return;
    int beg = g_soff[w];
    const float* row = g_GB + (size_t)w * NB;
    float G0[32], G1[32];
#pragma unroll
    for (int k = 0; k < 32; k++) {
        G0[k] = row[k * 64 + lane];
        G1[k] = row[k * 64 + 32 + lane];
    }
    float u0 = row[2112 + lane], u1 = row[2144 + lane];
    const float* rbase = g_r + (size_t)layer * EE * KH;
    for (int p = beg; p < beg + cnt; p++) {
        int e = g_csr[p];
        int d = dst[e];
        float rk = rbase[e * KH + lane];
        float a0 = u0, a1 = u1;
#pragma unroll
        for (int k = 0; k < 32; k++) {
            float rv = __shfl_sync(0xffffffffu, rk, k);
            a0 += rv * G0[k];
            a1 += rv * G1[k];
        }
        atomicAdd(&g_agg[d * H + lane], a0);
        atomicAdd(&g_agg[d * H + 32 + lane], a1);
    }
}

// ===================== norm passes =====================
__global__ __launch_bounds__(256) void k_pass1(const float* __restrict__ rb, int l) {
    __shared__ float rs[256], rs2[256];
    int tid = threadIdx.x;
    int o = tid & 63, g = tid >> 6;
    float s = 0.0f, s2 = 0.0f;
    int nbase = blockIdx.x * 64;
    for (int j = 0; j < 16; j++) {
        int n = nbase + j * 4 + g;
        if (n < NN) {
            int idx = n * H + o;
            float v = g_agg[idx] * g_invdeg[n] + g_GB[(size_t)n * NB + 2048 + o] + rb[o];
            g_hpre[idx] = v;
            s += v;
            s2 += v * v;
        }
    }
    rs[tid] = s;
    rs2[tid] = s2;
    __syncthreads();
    if (tid < 64) {
        float t = rs[tid] + rs[tid + 64] + rs[tid + 128] + rs[tid + 192];
        float t2 = rs2[tid] + rs2[tid + 64] + rs2[tid + 128] + rs2[tid + 192];
        atomicAdd(&g_colsum[l][tid], t);
        atomicAdd(&g_colsumsq[l][tid], t2);
    }
}
// finalize folded in: each thread recomputes norm scalars from per-layer colsums
__global__ void k_pass2(int l, float* __restrict__ out, const float* __restrict__ gw,
                        const float* __restrict__ gb, const float* __restrict__ gms) {
    int idx = blockIdx.x * blockDim.x + threadIdx.x;
    if (idx >= NN * H) return;
    int n = idx >> 6, o = idx & 63;
    float mean = g_colsum[l][o] * (1.0f / NN);
    float ex2 = g_colsumsq[l][o] * (1.0f / NN);
    float ms = gms[o];
    float var = ex2 - (2.0f * ms - ms * ms) * mean * mean;
    float a = gw[o] * rsqrtf(var + GEPS);
    float cc = gb[o] - a * ms * mean;
    float v = a * g_hpre[idx] + cc;
    if (l == 0) {
        v = (v > 0.0f) ? v : 0.2f * v;
        __nv_bfloat16 hi = __float2bfloat16(v);
        __nv_bfloat16 lo = __float2bfloat16(v - __bfloat162float(hi));
        g_A[n * KB + o] = hi;
        g_A[n * KB + 64 + o] = hi;
        g_A[n * KB + 128 + o] = lo;
        g_agg[idx] = 0.0f;
    } else {
        out[idx] = v;
    }
}

// ===================== launch =====================
extern "C" void kernel_launch(void* const* d_in, const int* in_sizes, int n_in,
                              void* d_out, int out_size) {
    const float* x      = (const float*)d_in[0];
    const int*   ei     = (const int*)d_in[1];
    const float* ea     = (const float*)d_in[2];
    const float* proj_w = (const float*)d_in[3];
    const float* proj_b = (const float*)d_in[4];
    const float* enn_w1 = (const float*)d_in[5];
    const float* enn_b1 = (const float*)d_in[6];
    const float* enn_w2 = (const float*)d_in[7];
    const float* enn_b2 = (const float*)d_in[8];
    const float* root_w = (const float*)d_in[9];
    const float* root_b = (const float*)d_in[10];
    const float* gn_w   = (const float*)d_in[11];
    const float* gn_b   = (const float*)d_in[12];
    const float* gn_ms  = (const float*)d_in[13];
    const int* src = ei;
    const int* dst = ei + EE;

    // immediate host-side attribute set (not a stream op; graph-capture safe, idempotent)
    cudaFuncSetAttribute(k_gemm, cudaFuncAttributeMaxDynamicSharedMemorySize, GSMEM);

    // launch #4 (= ncu capture slot) is k_gemm layer 0
    k_proj<<<(MPAD * H + 255) / 256, 256>>>(x, proj_w, proj_b);
    k_prep<<<(MLPN + 2 * NB * KB + 255) / 256, 256>>>(ea, enn_w1, enn_b1,
                                                      enn_w2, root_w, enn_b2);
    k_count<<<(EE + 255) / 256, 256>>>(src, dst);
    k_gemm<<<dim3(40, 17), 256, GSMEM>>>(0);
    k_offsets<<<(NN + 255) / 256, 256>>>();
    k_fill<<<(EE + 255) / 256, 256>>>(src);
    k_msg<<<(NN + 7) / 8, 256>>>(dst, 0);
    k_pass1<<<(NN + 63) / 64, 256>>>(root_b, 0);
    k_pass2<<<(NN * H + 255) / 256, 256>>>(0, (float*)d_out, gn_w, gn_b, gn_ms);
    k_gemm<<<dim3(40, 17), 256, GSMEM>>>(1);
    k_msg<<<(NN + 7) / 8, 256>>>(dst, 1);
    k_pass1<<<(NN + 63) / 64, 256>>>(root_b + H, 1);
    k_pass2<<<(NN * H + 255) / 256, 256>>>(1, (float*)d_out, gn_w + H, gn_b + H, gn_ms + H);
}

// round 10
// speedup vs baseline: 1.7405x; 1.0556x over previous
#include <cuda_runtime.h>
#include <cuda_bf16.h>
#include <cstdint>

#define NN 10000
#define MPAD 10240           // 40 * 256
#define EE 50000
#define IND 8
#define H 64
#define KH 32
#define KB 192               // stacked K: [h_hi | h_hi | h_lo]
#define NB 2176              // 2048 (G) + 64 (root_w base) + 64 (B2 u-term)
#define GEPS 1e-5f
#define NORMBLKS 125         // 125 * 80 = 10000, single wave guaranteed

// ===================== device scratch =====================
__device__ float g_agg[NN * H];
__device__ float g_r[2 * EE * KH];
__device__ __nv_bfloat16 g_A[MPAD * KB];            // [h_hi | h_hi | h_lo]
__device__ __nv_bfloat16 g_B[2 * NB * KB];          // per-layer [N-row][K] bf16
__device__ float g_GB[(size_t)MPAD * NB];           // GEMM output: G | base | u
__device__ int g_sdeg[NN], g_ddeg[NN];
__device__ int g_soff[NN], g_cursor[NN], g_csr[EE];
__device__ int g_total;
__device__ int g_done[2];
__device__ float g_invdeg[NN];
__device__ float g_colsum[2][H], g_colsumsq[2][H];

__device__ __forceinline__ uint32_t smem_u32(const void* p) {
    uint32_t a;
    asm("{ .reg .u64 t; cvta.to.shared.u64 t, %1; cvt.u32.u64 %0, t; }" : "=r"(a) : "l"(p));
    return a;
}

// ===================== setup kernels =====================
// h = x@proj_w+proj_b split into g_A [hi|hi|lo]; zero agg + counters
__global__ void k_proj(const float* __restrict__ x, const float* __restrict__ w,
                       const float* __restrict__ b) {
    int idx = blockIdx.x * blockDim.x + threadIdx.x;
    if (idx >= MPAD * H) return;
    if (idx < NN) { g_sdeg[idx] = 0; g_ddeg[idx] = 0; }
    if (idx < H) {
        g_colsum[0][idx] = 0.0f; g_colsumsq[0][idx] = 0.0f;
        g_colsum[1][idx] = 0.0f; g_colsumsq[1][idx] = 0.0f;
    }
    if (idx == 0) { g_total = 0; g_done[0] = 0; g_done[1] = 0; }
    int n = idx >> 6, o = idx & 63;
    float v = 0.0f;
    if (n < NN) {
        v = b[o];
#pragma unroll
        for (int i = 0; i < IND; i++) v += x[n * IND + i] * w[i * H + o];
        g_agg[idx] = 0.0f;
    }
    __nv_bfloat16 hi = __float2bfloat16(v);
    __nv_bfloat16 lo = __float2bfloat16(v - __bfloat162float(hi));
    g_A[n * KB + o] = hi;
    g_A[n * KB + 64 + o] = hi;
    g_A[n * KB + 128 + o] = lo;
}
__global__ void k_count(const int* __restrict__ src, const int* __restrict__ dst) {
    int i = blockIdx.x * blockDim.x + threadIdx.x;
    if (i < EE) { atomicAdd(&g_sdeg[src[i]], 1); atomicAdd(&g_ddeg[dst[i]], 1); }
}
// order-free CSR offsets
__global__ void k_offsets() {
    int i = blockIdx.x * blockDim.x + threadIdx.x;
    if (i >= NN) return;
    int d = g_sdeg[i];
    int pos = (d > 0) ? atomicAdd(&g_total, d) : 0;
    g_soff[i] = pos;
    g_cursor[i] = pos;
    g_invdeg[i] = 1.0f / fmaxf((float)g_ddeg[i], 1.0f);
}
__global__ void k_fill(const int* __restrict__ src) {
    int e = blockIdx.x * blockDim.x + threadIdx.x;
    if (e < EE) {
        int pos = atomicAdd(&g_cursor[src[e]], 1);
        g_csr[pos] = e;
    }
}
// merged: edge-MLP (both layers) + B matrix build (both layers)
#define MLPN (2 * EE * KH)
__global__ void k_prep(const float* __restrict__ ea, const float* __restrict__ w1,
                       const float* __restrict__ b1, const float* __restrict__ w2,
                       const float* __restrict__ rw, const float* __restrict__ b2) {
    int idx = blockIdx.x * blockDim.x + threadIdx.x;
    if (idx < MLPN) {
        int l = idx / (EE * KH);
        int rem = idx - l * (EE * KH);
        int e = rem >> 5, k = rem & 31;
        float acc = b1[l * KH + k];
#pragma unroll
        for (int d = 0; d < 4; d++) acc += ea[e * 4 + d] * w1[l * 128 + d * KH + k];
        g_r[idx] = fmaxf(acc, 0.0f);
        return;
    }
    int t = idx - MLPN;
    if (t >= 2 * NB * KB) return;
    int l = t / (NB * KB);
    int rem = t - l * (NB * KB);
    int c = rem / KB, k = rem - c * KB;
    int blk = k >> 6, i = k & 63;
    float S;
    if (c < 2048) S = w2[l * 131072 + (c >> 6) * 4096 + i * 64 + (c & 63)];
    else if (c < 2112) S = rw[l * 4096 + i * 64 + (c - 2048)];
    else S = b2[l * 4096 + i * 64 + (c - 2112)];
    __nv_bfloat16 hi = __float2bfloat16(S);
    __nv_bfloat16 v = (blk == 1) ? __float2bfloat16(S - __bfloat162float(hi)) : hi;
    g_B[t] = v;
}

// ===================== warp-MMA GEMM: 256x128, 3-stage cp.async + frag double-buffer =====================
__device__ __forceinline__ void mma_bf16(float* c, const uint32_t* a, const uint32_t* b) {
    asm volatile(
        "mma.sync.aligned.m16n8k16.row.col.f32.bf16.bf16.f32 "
        "{%0,%1,%2,%3}, {%4,%5,%6,%7}, {%8,%9}, {%0,%1,%2,%3};"
        : "+f"(c[0]), "+f"(c[1]), "+f"(c[2]), "+f"(c[3])
        : "r"(a[0]), "r"(a[1]), "r"(a[2]), "r"(a[3]), "r"(b[0]), "r"(b[1]));
}
__device__ __forceinline__ void ldmx4(uint32_t* r, uint32_t addr) {
    asm volatile("ldmatrix.sync.aligned.m8n8.x4.shared.b16 {%0,%1,%2,%3}, [%4];"
                 : "=r"(r[0]), "=r"(r[1]), "=r"(r[2]), "=r"(r[3]) : "r"(addr));
}
__device__ __forceinline__ void cp16(uint32_t sdst, const void* gsrc) {
    asm volatile("cp.async.ca.shared.global [%0], [%1], 16;" :: "r"(sdst), "l"(gsrc));
}
#define CPCOMMIT() asm volatile("cp.async.commit_group;" ::: "memory")
#define CPWAIT1() asm volatile("cp.async.wait_group 1;" ::: "memory")
#define CPWAIT0() asm volatile("cp.async.wait_group 0;" ::: "memory")

#define CH 16      // K elems per chunk -> 12 chunks
#define SST 24     // row stride (bf16) = 48B (cp.async-aligned); ldmatrix banks all distinct
#define STG (384 * SST)           // elems per stage (A rows 0..255, B rows 256..383)
#define GSMEM (3 * STG * 2)       // 55296 bytes dynamic smem

__global__ __launch_bounds__(256, 1) void k_gemm(int layer) {
    extern __shared__ __nv_bfloat16 sm[];   // [3][STG]
    int tid = threadIdx.x;
    int lane = tid & 31, w = tid >> 5;
    int wm = w >> 1, wn = w & 1;           // 4(M) x 2(N) warps, 64x64 each
    int g = lane >> 2, tc = lane & 3;
    int n0 = blockIdx.x * 256, nb0 = blockIdx.y * 128;
    const __nv_bfloat16* Bg = g_B + (size_t)layer * NB * KB;

    // cp.async slots: 3 per thread
    const __nv_bfloat16* gsrc[3];
    uint32_t sdst[3];
#pragma unroll
    for (int k = 0; k < 3; k++) {
        int slot = tid + k * 256;
        int row = slot >> 1, h = (slot & 1) * 8;
        gsrc[k] = (row < 256) ? g_A + (size_t)(n0 + row) * KB + h
                              : Bg + (size_t)(nb0 + row - 256) * KB + h;
        sdst[k] = smem_u32(&sm[row * SST + h]);
    }
#define ISSUE(c, st) do {                                               \
        uint32_t o = (uint32_t)(st) * (STG * 2);                        \
        cp16(sdst[0] + o, gsrc[0] + (c) * CH);                          \
        cp16(sdst[1] + o, gsrc[1] + (c) * CH);                          \
        cp16(sdst[2] + o, gsrc[2] + (c) * CH);                          \
    } while (0)

    // ldmatrix stage-0 base addresses
    int arow = (lane & 7) + ((lane >> 3) & 1) * 8;
    int acol = ((lane >> 4) & 1) * 8;
    int brow = (lane & 7) + ((lane >> 4) & 1) * 8;
    int bcol = ((lane >> 3) & 1) * 8;
    uint32_t aBase[4], bBase[4];
#pragma unroll
    for (int mi = 0; mi < 4; mi++)
        aBase[mi] = smem_u32(&sm[(wm * 64 + mi * 16 + arow) * SST + acol]);
#pragma unroll
    for (int p = 0; p < 4; p++)
        bBase[p] = smem_u32(&sm[(256 + wn * 64 + p * 16 + brow) * SST + bcol]);

    ISSUE(0, 0); CPCOMMIT();
    ISSUE(1, 1); CPCOMMIT();

    float acc[4][8][4] = {};
    uint32_t af[2][4][4], bq[2][4][4];

    // preload chunk 0 fragments
    CPWAIT1();
    __syncthreads();
#pragma unroll
    for (int mi = 0; mi < 4; mi++) ldmx4(af[0][mi], aBase[mi]);
#pragma unroll
    for (int p = 0; p < 4; p++) ldmx4(bq[0][p], bBase[p]);

#pragma unroll
    for (int c = 0; c < 12; c++) {
        int cur = c & 1, nxt = cur ^ 1;
        if (c + 2 < 12) { ISSUE(c + 2, (c + 2) % 3); CPCOMMIT(); }
        if (c + 1 < 12) {
            // need group (c+1) complete before its LDSM:
            // if group (c+2) was just committed it may remain pending (wait 1);
            // otherwise drain everything (wait 0). Tail bug fix vs R9.
            if (c + 2 < 12) CPWAIT1(); else CPWAIT0();
            __syncthreads();   // all warps' LDSM of stage (c-1) done & stage c+1 visible
            uint32_t so = (uint32_t)(((c + 1) % 3) * (STG * 2));
#pragma unroll
            for (int mi = 0; mi < 4; mi++) ldmx4(af[nxt][mi], aBase[mi] + so);
#pragma unroll
            for (int p = 0; p < 4; p++) ldmx4(bq[nxt][p], bBase[p] + so);
        }
        // MMAs on current fragments — independent of the LDSMs just issued
#pragma unroll
        for (int mi = 0; mi < 4; mi++)
#pragma unroll
            for (int ni = 0; ni < 8; ni++)
                mma_bf16(acc[mi][ni], af[cur][mi], &bq[cur][ni >> 1][(ni & 1) * 2]);
    }
    // epilogue: fragment-mapped direct stores
#pragma unroll
    for (int mi = 0; mi < 4; mi++) {
        int row0 = n0 + wm * 64 + mi * 16 + g;
#pragma unroll
        for (int ni = 0; ni < 8; ni++) {
            int col = nb0 + wn * 64 + ni * 8 + tc * 2;
            *(float2*)(g_GB + (size_t)row0 * NB + col) =
                make_float2(acc[mi][ni][0], acc[mi][ni][1]);
            *(float2*)(g_GB + (size_t)(row0 + 8) * NB + col) =
                make_float2(acc[mi][ni][2], acc[mi][ni][3]);
        }
    }
#undef ISSUE
}

// ===================== message pass: warp per src node, G row in registers =====================
__global__ __launch_bounds__(256) void k_msg(const int* __restrict__ dst, int layer) {
    int w = blockIdx.x * 8 + (threadIdx.x >> 5);
    int lane = threadIdx.x & 31;
    if (w >= NN) return;
    int cnt = g_sdeg[w];
    if (cnt == 0) return;
    int beg = g_soff[w];
    const float* row = g_GB + (size_t)w * NB;
    float G0[32], G1[32];
#pragma unroll
    for (int k = 0; k < 32; k++) {
        G0[k] = row[k * 64 + lane];
        G1[k] = row[k * 64 + 32 + lane];
    }
    float u0 = row[2112 + lane], u1 = row[2144 + lane];
    const float* rbase = g_r + (size_t)layer * EE * KH;
    for (int p = beg; p < beg + cnt; p++) {
        int e = g_csr[p];
        int d = dst[e];
        float rk = rbase[e * KH + lane];
        float a0 = u0, a1 = u1;
#pragma unroll
        for (int k = 0; k < 32; k++) {
            float rv = __shfl_sync(0xffffffffu, rk, k);
            a0 += rv * G0[k];
            a1 += rv * G1[k];
        }
        atomicAdd(&g_agg[d * H + lane], a0);
        atomicAdd(&g_agg[d * H + 32 + lane], a1);
    }
}

// ===================== fused norm: pass1 + finalize + pass2 (single-wave coop) =====================
__global__ __launch_bounds__(256) void k_norm(int l, float* __restrict__ out,
                                              const float* __restrict__ rb,
                                              const float* __restrict__ gw,
                                              const float* __restrict__ gb,
                                              const float* __restrict__ gms) {
    __shared__ float rs[256], rs2[256];
    int tid = threadIdx.x;
    int o = tid & 63, g = tid >> 6;
    int nbase = blockIdx.x * 80;
    float vloc[20];
    float s = 0.0f, s2 = 0.0f;
#pragma unroll
    for (int j = 0; j < 20; j++) {
        int n = nbase + j * 4 + g;                 // 125*80 == NN exactly
        int idx = n * H + o;
        float v = g_agg[idx] * g_invdeg[n] + g_GB[(size_t)n * NB + 2048 + o] + rb[o];
        vloc[j] = v;
        s += v;
        s2 += v * v;
    }
    rs[tid] = s;
    rs2[tid] = s2;
    __syncthreads();
    if (tid < 64) {
        float t = rs[tid] + rs[tid + 64] + rs[tid + 128] + rs[tid + 192];
        float t2 = rs2[tid] + rs2[tid + 64] + rs2[tid + 128] + rs2[tid + 192];
        atomicAdd(&g_colsum[l][tid], t);
        atomicAdd(&g_colsumsq[l][tid], t2);
        __threadfence();
    }
    __syncthreads();
    if (tid == 0) {
        atomicAdd(&g_done[l], 1);
        while (atomicAdd(&g_done[l], 0) < NORMBLKS) {}
    }
    __syncthreads();
    // volatile: bypass L1 — other blocks' atomics landed in L2
    volatile float* cs = g_colsum[l];
    volatile float* cs2 = g_colsumsq[l];
    float mean = cs[o] * (1.0f / NN);
    float ex2 = cs2[o] * (1.0f / NN);
    float ms = gms[o];
    float var = ex2 - (2.0f * ms - ms * ms) * mean * mean;
    float a = gw[o] * rsqrtf(var + GEPS);
    float cc = gb[o] - a * ms * mean;
#pragma unroll
    for (int j = 0; j < 20; j++) {
        int n = nbase + j * 4 + g;
        int idx = n * H + o;
        float v = a * vloc[j] + cc;
        if (l == 0) {
            v = (v > 0.0f) ? v : 0.2f * v;
            __nv_bfloat16 hi = __float2bfloat16(v);
            __nv_bfloat16 lo = __float2bfloat16(v - __bfloat162float(hi));
            g_A[n * KB + o] = hi;
            g_A[n * KB + 64 + o] = hi;
            g_A[n * KB + 128 + o] = lo;
            g_agg[idx] = 0.0f;
        } else {
            out[idx] = v;
        }
    }
}

// ===================== launch =====================
extern "C" void kernel_launch(void* const* d_in, const int* in_sizes, int n_in,
                              void* d_out, int out_size) {
    const float* x      = (const float*)d_in[0];
    const int*   ei     = (const int*)d_in[1];
    const float* ea     = (const float*)d_in[2];
    const float* proj_w = (const float*)d_in[3];
    const float* proj_b = (const float*)d_in[4];
    const float* enn_w1 = (const float*)d_in[5];
    const float* enn_b1 = (const float*)d_in[6];
    const float* enn_w2 = (const float*)d_in[7];
    const float* enn_b2 = (const float*)d_in[8];
    const float* root_w = (const float*)d_in[9];
    const float* root_b = (const float*)d_in[10];
    const float* gn_w   = (const float*)d_in[11];
    const float* gn_b   = (const float*)d_in[12];
    const float* gn_ms  = (const float*)d_in[13];
    const int* src = ei;
    const int* dst = ei + EE;

    cudaFuncSetAttribute(k_gemm, cudaFuncAttributeMaxDynamicSharedMemorySize, GSMEM);

    // launch #4 (= ncu capture slot) is k_gemm layer 0
    k_proj<<<(MPAD * H + 255) / 256, 256>>>(x, proj_w, proj_b);
    k_prep<<<(MLPN + 2 * NB * KB + 255) / 256, 256>>>(ea, enn_w1, enn_b1,
                                                      enn_w2, root_w, enn_b2);
    k_count<<<(EE + 255) / 256, 256>>>(src, dst);
    k_gemm<<<dim3(40, 17), 256, GSMEM>>>(0);
    k_offsets<<<(NN + 255) / 256, 256>>>();
    k_fill<<<(EE + 255) / 256, 256>>>(src);
    k_msg<<<(NN + 7) / 8, 256>>>(dst, 0);
    k_norm<<<NORMBLKS, 256>>>(0, (float*)d_out, root_b, gn_w, gn_b, gn_ms);
    k_gemm<<<dim3(40, 17), 256, GSMEM>>>(1);
    k_msg<<<(NN + 7) / 8, 256>>>(dst, 1);
    k_norm<<<NORMBLKS, 256>>>(1, (float*)d_out, root_b + H, gn_w + H, gn_b + H, gn_ms + H);
}

// round 11
// speedup vs baseline: 1.9263x; 1.1067x over previous
#include <cuda_runtime.h>
#include <cuda_fp16.h>
#include <cstdint>

#define NN 10000
#define MPAD 10240           // 40 * 256
#define EE 50000
#define IND 8
#define H 64
#define KH 32
#define KB 128               // stacked K: [h_hi | h_lo] (fp16 split)
#define NB 2176              // 2048 (G) + 64 (root_w base) + 64 (B2 u-term)
#define GEPS 1e-5f
#define NORMBLKS 125         // 125 * 80 = 10000, single wave
#define CSRBLKS 125

// ===================== device scratch =====================
__device__ float g_agg[NN * H];
__device__ float g_r[2 * EE * KH];
__device__ __half g_A[MPAD * KB];                   // [h_hi | h_lo]
__device__ __half g_B[2 * NB * KB];                 // per-layer [N-row][K]: [W_hi ; W_hi]
__device__ float g_GB[(size_t)MPAD * NB];           // GEMM output: G | base | u
__device__ int g_sdeg[NN], g_ddeg[NN];
__device__ int g_soff[NN], g_cursor[NN], g_csr[EE];
__device__ int g_total;
__device__ int g_done[3];                           // [0],[1]=norm layers, [2]=csr
__device__ float g_invdeg[NN];
__device__ float g_colsum[2][H], g_colsumsq[2][H];

__device__ __forceinline__ uint32_t smem_u32(const void* p) {
    uint32_t a;
    asm("{ .reg .u64 t; cvta.to.shared.u64 t, %1; cvt.u32.u64 %0, t; }" : "=r"(a) : "l"(p));
    return a;
}
__device__ __forceinline__ void gridbar(int* ctr, int target) {
    __threadfence();
    __syncthreads();
    if (threadIdx.x == 0) {
        atomicAdd(ctr, 1);
        while (atomicAdd(ctr, 0) < target) {}
    }
    __syncthreads();
}

// ===================== setup kernels =====================
// h = x@proj_w+proj_b split into g_A [hi|lo]; zero agg + counters
__global__ void k_proj(const float* __restrict__ x, const float* __restrict__ w,
                       const float* __restrict__ b) {
    int idx = blockIdx.x * blockDim.x + threadIdx.x;
    if (idx >= MPAD * H) return;
    if (idx < NN) { g_sdeg[idx] = 0; g_ddeg[idx] = 0; }
    if (idx < H) {
        g_colsum[0][idx] = 0.0f; g_colsumsq[0][idx] = 0.0f;
        g_colsum[1][idx] = 0.0f; g_colsumsq[1][idx] = 0.0f;
    }
    if (idx == 0) { g_total = 0; g_done[0] = 0; g_done[1] = 0; g_done[2] = 0; }
    int n = idx >> 6, o = idx & 63;
    float v = 0.0f;
    if (n < NN) {
        v = b[o];
#pragma unroll
        for (int i = 0; i < IND; i++) v += x[n * IND + i] * w[i * H + o];
        g_agg[idx] = 0.0f;
    }
    __half hi = __float2half_rn(v);
    __half lo = __float2half_rn(v - __half2float(hi));
    g_A[n * KB + o] = hi;
    g_A[n * KB + 64 + o] = lo;
}
// merged: edge-MLP (both layers) + B build (both layers) + degree count
#define MLPN (2 * EE * KH)
#define BTOT (2 * NB * KB)
#define PREPTOT (MLPN + BTOT + EE)
__global__ void k_prep(const float* __restrict__ ea, const float* __restrict__ w1,
                       const float* __restrict__ b1, const float* __restrict__ w2,
                       const float* __restrict__ rw, const float* __restrict__ b2,
                       const int* __restrict__ src, const int* __restrict__ dst) {
    int idx = blockIdx.x * blockDim.x + threadIdx.x;
    if (idx < MLPN) {
        int l = idx / (EE * KH);
        int rem = idx - l * (EE * KH);
        int e = rem >> 5, k = rem & 31;
        float acc = b1[l * KH + k];
#pragma unroll
        for (int d = 0; d < 4; d++) acc += ea[e * 4 + d] * w1[l * 128 + d * KH + k];
        g_r[idx] = fmaxf(acc, 0.0f);
        return;
    }
    int t = idx - MLPN;
    if (t < BTOT) {
        int l = t / (NB * KB);
        int rem = t - l * (NB * KB);
        int c = rem / KB, k = rem - c * KB;
        int i = k & 63;   // both K-blocks hold W_hi
        float S;
        if (c < 2048) S = w2[l * 131072 + (c >> 6) * 4096 + i * 64 + (c & 63)];
        else if (c < 2112) S = rw[l * 4096 + i * 64 + (c - 2048)];
        else S = b2[l * 4096 + i * 64 + (c - 2112)];
        g_B[t] = __float2half_rn(S);
        return;
    }
    int e = t - BTOT;
    if (e < EE) { atomicAdd(&g_sdeg[src[e]], 1); atomicAdd(&g_ddeg[dst[e]], 1); }
}
// single-kernel CSR build: offsets -> grid barrier -> fill
__global__ __launch_bounds__(256) void k_csr(const int* __restrict__ src) {
    int base = blockIdx.x * blockDim.x + threadIdx.x;
    for (int i = base; i < NN; i += CSRBLKS * 256) {
        int d = g_sdeg[i];
        int pos = (d > 0) ? atomicAdd(&g_total, d) : 0;
        g_soff[i] = pos;
        g_cursor[i] = pos;
        g_invdeg[i] = 1.0f / fmaxf((float)g_ddeg[i], 1.0f);
    }
    gridbar(&g_done[2], CSRBLKS);
    for (int e = base; e < EE; e += CSRBLKS * 256) {
        int pos = atomicAdd(&g_cursor[src[e]], 1);
        g_csr[pos] = e;
    }
}

// ===================== warp-MMA GEMM: 256x128, fp16, 3-stage cp.async =====================
__device__ __forceinline__ void mma_f16(float* c, const uint32_t* a, const uint32_t* b) {
    asm volatile(
        "mma.sync.aligned.m16n8k16.row.col.f32.f16.f16.f32 "
        "{%0,%1,%2,%3}, {%4,%5,%6,%7}, {%8,%9}, {%0,%1,%2,%3};"
        : "+f"(c[0]), "+f"(c[1]), "+f"(c[2]), "+f"(c[3])
        : "r"(a[0]), "r"(a[1]), "r"(a[2]), "r"(a[3]), "r"(b[0]), "r"(b[1]));
}
__device__ __forceinline__ void ldmx4(uint32_t* r, uint32_t addr) {
    asm volatile("ldmatrix.sync.aligned.m8n8.x4.shared.b16 {%0,%1,%2,%3}, [%4];"
                 : "=r"(r[0]), "=r"(r[1]), "=r"(r[2]), "=r"(r[3]) : "r"(addr));
}
__device__ __forceinline__ void cp16(uint32_t sdst, const void* gsrc) {
    asm volatile("cp.async.ca.shared.global [%0], [%1], 16;" :: "r"(sdst), "l"(gsrc));
}
#define CPCOMMIT() asm volatile("cp.async.commit_group;" ::: "memory")
#define CPWAIT1() asm volatile("cp.async.wait_group 1;" ::: "memory")
#define CPWAIT0() asm volatile("cp.async.wait_group 0;" ::: "memory")

#define CH 16      // K elems per chunk -> 8 chunks
#define NCHUNK 8
#define SST 24     // row stride (halves) = 48B; cp.async-aligned; ldmatrix conflict-free
#define STG (384 * SST)           // elems per stage
#define GSMEM (3 * STG * 2)       // 55296 B dynamic smem

__global__ __launch_bounds__(256, 1) void k_gemm(int layer) {
    extern __shared__ __half sm[];   // [3][STG]
    int tid = threadIdx.x;
    int lane = tid & 31, w = tid >> 5;
    int wm = w >> 1, wn = w & 1;           // 4(M) x 2(N) warps, 64x64 each
    int g = lane >> 2, tc = lane & 3;
    int n0 = blockIdx.x * 256, nb0 = blockIdx.y * 128;
    const __half* Bg = g_B + (size_t)layer * NB * KB;

    const __half* gsrc[3];
    uint32_t sdst[3];
#pragma unroll
    for (int k = 0; k < 3; k++) {
        int slot = tid + k * 256;
        int row = slot >> 1, h = (slot & 1) * 8;
        gsrc[k] = (row < 256) ? g_A + (size_t)(n0 + row) * KB + h
                              : Bg + (size_t)(nb0 + row - 256) * KB + h;
        sdst[k] = smem_u32(&sm[row * SST + h]);
    }
#define ISSUE(c, st) do {                                               \
        uint32_t o = (uint32_t)(st) * (STG * 2);                        \
        cp16(sdst[0] + o, gsrc[0] + (c) * CH);                          \
        cp16(sdst[1] + o, gsrc[1] + (c) * CH);                          \
        cp16(sdst[2] + o, gsrc[2] + (c) * CH);                          \
    } while (0)

    int arow = (lane & 7) + ((lane >> 3) & 1) * 8;
    int acol = ((lane >> 4) & 1) * 8;
    int brow = (lane & 7) + ((lane >> 4) & 1) * 8;
    int bcol = ((lane >> 3) & 1) * 8;
    uint32_t aBase[4], bBase[4];
#pragma unroll
    for (int mi = 0; mi < 4; mi++)
        aBase[mi] = smem_u32(&sm[(wm * 64 + mi * 16 + arow) * SST + acol]);
#pragma unroll
    for (int p = 0; p < 4; p++)
        bBase[p] = smem_u32(&sm[(256 + wn * 64 + p * 16 + brow) * SST + bcol]);

    ISSUE(0, 0); CPCOMMIT();
    ISSUE(1, 1); CPCOMMIT();

    float acc[4][8][4] = {};
    uint32_t af[2][4][4], bq[2][4][4];

    CPWAIT1();
    __syncthreads();
#pragma unroll
    for (int mi = 0; mi < 4; mi++) ldmx4(af[0][mi], aBase[mi]);
#pragma unroll
    for (int p = 0; p < 4; p++) ldmx4(bq[0][p], bBase[p]);

#pragma unroll
    for (int c = 0; c < NCHUNK; c++) {
        int cur = c & 1, nxt = cur ^ 1;
        if (c + 2 < NCHUNK) { ISSUE(c + 2, (c + 2) % 3); CPCOMMIT(); }
        if (c + 1 < NCHUNK) {
            if (c + 2 < NCHUNK) CPWAIT1(); else CPWAIT0();   // tail-correct drain
            __syncthreads();
            uint32_t so = (uint32_t)(((c + 1) % 3) * (STG * 2));
#pragma unroll
            for (int mi = 0; mi < 4; mi++) ldmx4(af[nxt][mi], aBase[mi] + so);
#pragma unroll
            for (int p = 0; p < 4; p++) ldmx4(bq[nxt][p], bBase[p] + so);
        }
#pragma unroll
        for (int mi = 0; mi < 4; mi++)
#pragma unroll
            for (int ni = 0; ni < 8; ni++)
                mma_f16(acc[mi][ni], af[cur][mi], &bq[cur][ni >> 1][(ni & 1) * 2]);
    }
#pragma unroll
    for (int mi = 0; mi < 4; mi++) {
        int row0 = n0 + wm * 64 + mi * 16 + g;
#pragma unroll
        for (int ni = 0; ni < 8; ni++) {
            int col = nb0 + wn * 64 + ni * 8 + tc * 2;
            *(float2*)(g_GB + (size_t)row0 * NB + col) =
                make_float2(acc[mi][ni][0], acc[mi][ni][1]);
            *(float2*)(g_GB + (size_t)(row0 + 8) * NB + col) =
                make_float2(acc[mi][ni][2], acc[mi][ni][3]);
        }
    }
#undef ISSUE
}

// ===================== message pass: warp per src node, G row in registers =====================
__global__ __launch_bounds__(256) void k_msg(const int* __restrict__ dst, int layer) {
    int w = blockIdx.x * 8 + (threadIdx.x >> 5);
    int lane = threadIdx.x & 31;
    if (w >= NN) return;
    int cnt = g_sdeg[w];
    if (cnt == 0) return;
    int beg = g_soff[w];
    const float* row = g_GB + (size_t)w * NB;
    float G0[32], G1[32];
#pragma unroll
    for (int k = 0; k < 32; k++) {
        G0[k] = row[k * 64 + lane];
        G1[k] = row[k * 64 + 32 + lane];
    }
    float u0 = row[2112 + lane], u1 = row[2144 + lane];
    const float* rbase = g_r + (size_t)layer * EE * KH;
    for (int p = beg; p < beg + cnt; p++) {
        int e = g_csr[p];
        int d = dst[e];
        float rk = rbase[e * KH + lane];
        float a0 = u0, a1 = u1;
#pragma unroll
        for (int k = 0; k < 32; k++) {
            float rv = __shfl_sync(0xffffffffu, rk, k);
            a0 += rv * G0[k];
            a1 += rv * G1[k];
        }
        atomicAdd(&g_agg[d * H + lane], a0);
        atomicAdd(&g_agg[d * H + 32 + lane], a1);
    }
}

// ===================== fused norm (single-wave coop) =====================
__global__ __launch_bounds__(256) void k_norm(int l, float* __restrict__ out,
                                              const float* __restrict__ rb,
                                              const float* __restrict__ gw,
                                              const float* __restrict__ gb,
                                              const float* __restrict__ gms) {
    __shared__ float rs[256], rs2[256];
    int tid = threadIdx.x;
    int o = tid & 63, g = tid >> 6;
    int nbase = blockIdx.x * 80;
    float vloc[20];
    float s = 0.0f, s2 = 0.0f;
#pragma unroll
    for (int j = 0; j < 20; j++) {
        int n = nbase + j * 4 + g;
        int idx = n * H + o;
        float v = g_agg[idx] * g_invdeg[n] + g_GB[(size_t)n * NB + 2048 + o] + rb[o];
        vloc[j] = v;
        s += v;
        s2 += v * v;
    }
    rs[tid] = s;
    rs2[tid] = s2;
    __syncthreads();
    if (tid < 64) {
        float t = rs[tid] + rs[tid + 64] + rs[tid + 128] + rs[tid + 192];
        float t2 = rs2[tid] + rs2[tid + 64] + rs2[tid + 128] + rs2[tid + 192];
        atomicAdd(&g_colsum[l][tid], t);
        atomicAdd(&g_colsumsq[l][tid], t2);
        __threadfence();
    }
    __syncthreads();
    if (tid == 0) {
        atomicAdd(&g_done[l], 1);
        while (atomicAdd(&g_done[l], 0) < NORMBLKS) {}
    }
    __syncthreads();
    volatile float* cs = g_colsum[l];
    volatile float* cs2 = g_colsumsq[l];
    float mean = cs[o] * (1.0f / NN);
    float ex2 = cs2[o] * (1.0f / NN);
    float ms = gms[o];
    float var = ex2 - (2.0f * ms - ms * ms) * mean * mean;
    float a = gw[o] * rsqrtf(var + GEPS);
    float cc = gb[o] - a * ms * mean;
#pragma unroll
    for (int j = 0; j < 20; j++) {
        int n = nbase + j * 4 + g;
        int idx = n * H + o;
        float v = a * vloc[j] + cc;
        if (l == 0) {
            v = (v > 0.0f) ? v : 0.2f * v;
            __half hi = __float2half_rn(v);
            __half lo = __float2half_rn(v - __half2float(hi));
            g_A[n * KB + o] = hi;
            g_A[n * KB + 64 + o] = lo;
            g_agg[idx] = 0.0f;
        } else {
            out[idx] = v;
        }
    }
}

// ===================== launch =====================
extern "C" void kernel_launch(void* const* d_in, const int* in_sizes, int n_in,
                              void* d_out, int out_size) {
    const float* x      = (const float*)d_in[0];
    const int*   ei     = (const int*)d_in[1];
    const float* ea     = (const float*)d_in[2];
    const float* proj_w = (const float*)d_in[3];
    const float* proj_b = (const float*)d_in[4];
    const float* enn_w1 = (const float*)d_in[5];
    const float* enn_b1 = (const float*)d_in[6];
    const float* enn_w2 = (const float*)d_in[7];
    const float* enn_b2 = (const float*)d_in[8];
    const float* root_w = (const float*)d_in[9];
    const float* root_b = (const float*)d_in[10];
    const float* gn_w   = (const float*)d_in[11];
    const float* gn_b   = (const float*)d_in[12];
    const float* gn_ms  = (const float*)d_in[13];
    const int* src = ei;
    const int* dst = ei + EE;

    cudaFuncSetAttribute(k_gemm, cudaFuncAttributeMaxDynamicSharedMemorySize, GSMEM);

    // launch #4 (= ncu capture slot) is k_gemm layer 0
    k_proj<<<(MPAD * H + 255) / 256, 256>>>(x, proj_w, proj_b);
    k_prep<<<(PREPTOT + 255) / 256, 256>>>(ea, enn_w1, enn_b1, enn_w2, root_w, enn_b2,
                                           src, dst);
    k_csr<<<CSRBLKS, 256>>>(src);
    k_gemm<<<dim3(40, 17), 256, GSMEM>>>(0);
    k_msg<<<(NN + 7) / 8, 256>>>(dst, 0);
    k_norm<<<NORMBLKS, 256>>>(0, (float*)d_out, root_b, gn_w, gn_b, gn_ms);
    k_gemm<<<dim3(40, 17), 256, GSMEM>>>(1);
    k_msg<<<(NN + 7) / 8, 256>>>(dst, 1);
    k_norm<<<NORMBLKS, 256>>>(1, (float*)d_out, root_b + H, gn_w + H, gn_b + H, gn_ms + H);
}

// round 12
// speedup vs baseline: 2.2304x; 1.1579x over previous
#include <cuda_runtime.h>
#include <cuda_fp16.h>
#include <cstdint>

#define NN 10000
#define MPAD 10240           // 40 * 256
#define EE 50000
#define IND 8
#define H 64
#define KH 32
#define KB 128               // stacked K: [h_hi | h_lo] (fp16 split)
#define NB 2176              // 2048 (G) + 64 (root_w base) + 64 (B2 u-term)
#define GEPS 1e-5f
#define NORMBLKS 125         // 125 * 80 = 10000, single wave
#define CSRBLKS 125

// ===================== device scratch =====================
__device__ float g_agg[NN * H];
__device__ float g_r[2 * EE * KH];
__device__ __half g_A[MPAD * KB];                   // [h_hi | h_lo]
__device__ __half g_B[2 * NB * KB];                 // per-layer [N-row][K]: [W_hi ; W_hi]
__device__ __half g_Gh[(size_t)MPAD * 2048];        // GEMM output G, fp16 (42 MB)
__device__ float g_base[MPAD * 128];                // GEMM output base|u, fp32
__device__ int g_sdeg[NN], g_ddeg[NN];
__device__ int g_soff[NN], g_cursor[NN], g_csr[EE];
__device__ int g_total;
__device__ int g_done[3];                           // [0],[1]=norm layers, [2]=csr
__device__ float g_invdeg[NN];
__device__ float g_colsum[2][H], g_colsumsq[2][H];

__device__ __forceinline__ uint32_t smem_u32(const void* p) {
    uint32_t a;
    asm("{ .reg .u64 t; cvta.to.shared.u64 t, %1; cvt.u32.u64 %0, t; }" : "=r"(a) : "l"(p));
    return a;
}
__device__ __forceinline__ void gridbar(int* ctr, int target) {
    __threadfence();
    __syncthreads();
    if (threadIdx.x == 0) {
        atomicAdd(ctr, 1);
        while (atomicAdd(ctr, 0) < target) {}
    }
    __syncthreads();
}

// ===================== setup kernels =====================
// h = x@proj_w+proj_b split into g_A [hi|lo]; zero agg + counters
__global__ void k_proj(const float* __restrict__ x, const float* __restrict__ w,
                       const float* __restrict__ b) {
    int idx = blockIdx.x * blockDim.x + threadIdx.x;
    if (idx >= MPAD * H) return;
    if (idx < NN) { g_sdeg[idx] = 0; g_ddeg[idx] = 0; }
    if (idx < H) {
        g_colsum[0][idx] = 0.0f; g_colsumsq[0][idx] = 0.0f;
        g_colsum[1][idx] = 0.0f; g_colsumsq[1][idx] = 0.0f;
    }
    if (idx == 0) { g_total = 0; g_done[0] = 0; g_done[1] = 0; g_done[2] = 0; }
    int n = idx >> 6, o = idx & 63;
    float v = 0.0f;
    if (n < NN) {
        v = b[o];
#pragma unroll
        for (int i = 0; i < IND; i++) v += x[n * IND + i] * w[i * H + o];
        g_agg[idx] = 0.0f;
    }
    __half hi = __float2half_rn(v);
    __half lo = __float2half_rn(v - __half2float(hi));
    g_A[n * KB + o] = hi;
    g_A[n * KB + 64 + o] = lo;
}
// merged: edge-MLP (both layers) + B build (both layers) + degree count
#define MLPN (2 * EE * KH)
#define BTOT (2 * NB * KB)
#define PREPTOT (MLPN + BTOT + EE)
__global__ void k_prep(const float* __restrict__ ea, const float* __restrict__ w1,
                       const float* __restrict__ b1, const float* __restrict__ w2,
                       const float* __restrict__ rw, const float* __restrict__ b2,
                       const int* __restrict__ src, const int* __restrict__ dst) {
    int idx = blockIdx.x * blockDim.x + threadIdx.x;
    if (idx < MLPN) {
        int l = idx / (EE * KH);
        int rem = idx - l * (EE * KH);
        int e = rem >> 5, k = rem & 31;
        float acc = b1[l * KH + k];
#pragma unroll
        for (int d = 0; d < 4; d++) acc += ea[e * 4 + d] * w1[l * 128 + d * KH + k];
        g_r[idx] = fmaxf(acc, 0.0f);
        return;
    }
    int t = idx - MLPN;
    if (t < BTOT) {
        int l = t / (NB * KB);
        int rem = t - l * (NB * KB);
        int c = rem / KB, k = rem - c * KB;
        int i = k & 63;   // both K-blocks hold W_hi
        float S;
        if (c < 2048) S = w2[l * 131072 + (c >> 6) * 4096 + i * 64 + (c & 63)];
        else if (c < 2112) S = rw[l * 4096 + i * 64 + (c - 2048)];
        else S = b2[l * 4096 + i * 64 + (c - 2112)];
        g_B[t] = __float2half_rn(S);
        return;
    }
    int e = t - BTOT;
    if (e < EE) { atomicAdd(&g_sdeg[src[e]], 1); atomicAdd(&g_ddeg[dst[e]], 1); }
}
// single-kernel CSR build: offsets -> grid barrier -> fill
__global__ __launch_bounds__(256) void k_csr(const int* __restrict__ src) {
    int base = blockIdx.x * blockDim.x + threadIdx.x;
    for (int i = base; i < NN; i += CSRBLKS * 256) {
        int d = g_sdeg[i];
        int pos = (d > 0) ? atomicAdd(&g_total, d) : 0;
        g_soff[i] = pos;
        g_cursor[i] = pos;
        g_invdeg[i] = 1.0f / fmaxf((float)g_ddeg[i], 1.0f);
    }
    gridbar(&g_done[2], CSRBLKS);
    for (int e = base; e < EE; e += CSRBLKS * 256) {
        int pos = atomicAdd(&g_cursor[src[e]], 1);
        g_csr[pos] = e;
    }
}

// ===================== warp-MMA GEMM: 256x128, fp16, 3-stage cp.async =====================
__device__ __forceinline__ void mma_f16(float* c, const uint32_t* a, const uint32_t* b) {
    asm volatile(
        "mma.sync.aligned.m16n8k16.row.col.f32.f16.f16.f32 "
        "{%0,%1,%2,%3}, {%4,%5,%6,%7}, {%8,%9}, {%0,%1,%2,%3};"
        : "+f"(c[0]), "+f"(c[1]), "+f"(c[2]), "+f"(c[3])
        : "r"(a[0]), "r"(a[1]), "r"(a[2]), "r"(a[3]), "r"(b[0]), "r"(b[1]));
}
__device__ __forceinline__ void ldmx4(uint32_t* r, uint32_t addr) {
    asm volatile("ldmatrix.sync.aligned.m8n8.x4.shared.b16 {%0,%1,%2,%3}, [%4];"
                 : "=r"(r[0]), "=r"(r[1]), "=r"(r[2]), "=r"(r[3]) : "r"(addr));
}
__device__ __forceinline__ void cp16(uint32_t sdst, const void* gsrc) {
    asm volatile("cp.async.ca.shared.global [%0], [%1], 16;" :: "r"(sdst), "l"(gsrc));
}
#define CPCOMMIT() asm volatile("cp.async.commit_group;" ::: "memory")
#define CPWAIT1() asm volatile("cp.async.wait_group 1;" ::: "memory")
#define CPWAIT0() asm volatile("cp.async.wait_group 0;" ::: "memory")

#define CH 16      // K elems per chunk -> 8 chunks
#define NCHUNK 8
#define SST 24     // row stride (halves) = 48B; cp.async-aligned; ldmatrix conflict-free
#define STG (384 * SST)           // elems per stage
#define GSMEM (3 * STG * 2)       // 55296 B dynamic smem

__global__ __launch_bounds__(256, 1) void k_gemm(int layer) {
    extern __shared__ __half sm[];   // [3][STG]
    int tid = threadIdx.x;
    int lane = tid & 31, w = tid >> 5;
    int wm = w >> 1, wn = w & 1;           // 4(M) x 2(N) warps, 64x64 each
    int g = lane >> 2, tc = lane & 3;
    int n0 = blockIdx.x * 256, nb0 = blockIdx.y * 128;
    const __half* Bg = g_B + (size_t)layer * NB * KB;

    const __half* gsrc[3];
    uint32_t sdst[3];
#pragma unroll
    for (int k = 0; k < 3; k++) {
        int slot = tid + k * 256;
        int row = slot >> 1, h = (slot & 1) * 8;
        gsrc[k] = (row < 256) ? g_A + (size_t)(n0 + row) * KB + h
                              : Bg + (size_t)(nb0 + row - 256) * KB + h;
        sdst[k] = smem_u32(&sm[row * SST + h]);
    }
#define ISSUE(c, st) do {                                               \
        uint32_t o = (uint32_t)(st) * (STG * 2);                        \
        cp16(sdst[0] + o, gsrc[0] + (c) * CH);                          \
        cp16(sdst[1] + o, gsrc[1] + (c) * CH);                          \
        cp16(sdst[2] + o, gsrc[2] + (c) * CH);                          \
    } while (0)

    int arow = (lane & 7) + ((lane >> 3) & 1) * 8;
    int acol = ((lane >> 4) & 1) * 8;
    int brow = (lane & 7) + ((lane >> 4) & 1) * 8;
    int bcol = ((lane >> 3) & 1) * 8;
    uint32_t aBase[4], bBase[4];
#pragma unroll
    for (int mi = 0; mi < 4; mi++)
        aBase[mi] = smem_u32(&sm[(wm * 64 + mi * 16 + arow) * SST + acol]);
#pragma unroll
    for (int p = 0; p < 4; p++)
        bBase[p] = smem_u32(&sm[(256 + wn * 64 + p * 16 + brow) * SST + bcol]);

    ISSUE(0, 0); CPCOMMIT();
    ISSUE(1, 1); CPCOMMIT();

    float acc[4][8][4] = {};
    uint32_t af[2][4][4], bq[2][4][4];

    CPWAIT1();
    __syncthreads();
#pragma unroll
    for (int mi = 0; mi < 4; mi++) ldmx4(af[0][mi], aBase[mi]);
#pragma unroll
    for (int p = 0; p < 4; p++) ldmx4(bq[0][p], bBase[p]);

#pragma unroll
    for (int c = 0; c < NCHUNK; c++) {
        int cur = c & 1, nxt = cur ^ 1;
        if (c + 2 < NCHUNK) { ISSUE(c + 2, (c + 2) % 3); CPCOMMIT(); }
        if (c + 1 < NCHUNK) {
            if (c + 2 < NCHUNK) CPWAIT1(); else CPWAIT0();   // tail-correct drain
            __syncthreads();
            uint32_t so = (uint32_t)(((c + 1) % 3) * (STG * 2));
#pragma unroll
            for (int mi = 0; mi < 4; mi++) ldmx4(af[nxt][mi], aBase[mi] + so);
#pragma unroll
            for (int p = 0; p < 4; p++) ldmx4(bq[nxt][p], bBase[p] + so);
        }
#pragma unroll
        for (int mi = 0; mi < 4; mi++)
#pragma unroll
            for (int ni = 0; ni < 8; ni++)
                mma_f16(acc[mi][ni], af[cur][mi], &bq[cur][ni >> 1][(ni & 1) * 2]);
    }
    // epilogue: G tiles (y<16) pack fp16; base/u tile (y==16) stays fp32
    if (nb0 < 2048) {
#pragma unroll
        for (int mi = 0; mi < 4; mi++) {
            int row0 = n0 + wm * 64 + mi * 16 + g;
#pragma unroll
            for (int ni = 0; ni < 8; ni++) {
                int col = nb0 + wn * 64 + ni * 8 + tc * 2;
                *(__half2*)(g_Gh + (size_t)row0 * 2048 + col) =
                    __floats2half2_rn(acc[mi][ni][0], acc[mi][ni][1]);
                *(__half2*)(g_Gh + (size_t)(row0 + 8) * 2048 + col) =
                    __floats2half2_rn(acc[mi][ni][2], acc[mi][ni][3]);
            }
        }
    } else {
#pragma unroll
        for (int mi = 0; mi < 4; mi++) {
            int row0 = n0 + wm * 64 + mi * 16 + g;
#pragma unroll
            for (int ni = 0; ni < 8; ni++) {
                int col = wn * 64 + ni * 8 + tc * 2;   // 0..127 within base|u
                *(float2*)(g_base + (size_t)row0 * 128 + col) =
                    make_float2(acc[mi][ni][0], acc[mi][ni][1]);
                *(float2*)(g_base + (size_t)(row0 + 8) * 128 + col) =
                    make_float2(acc[mi][ni][2], acc[mi][ni][3]);
            }
        }
    }
#undef ISSUE
}

// ===================== message pass: warp per src node, fp16 G in registers =====================
// lane owns adjacent cols {2*lane, 2*lane+1}
__global__ __launch_bounds__(256) void k_msg(const int* __restrict__ dst, int layer) {
    int w = blockIdx.x * 8 + (threadIdx.x >> 5);
    int lane = threadIdx.x & 31;
    if (w >= NN) return;
    int cnt = g_sdeg[w];
    if (cnt == 0) return;
    int beg = g_soff[w];
    const __half* row = g_Gh + (size_t)w * 2048;
    float G0[32], G1[32];   // G0[k]=col 2l, G1[k]=col 2l+1
#pragma unroll
    for (int k = 0; k < 32; k++) {
        __half2 h2 = *(const __half2*)(row + k * 64 + 2 * lane);
        float2 f2 = __half22float2(h2);
        G0[k] = f2.x;
        G1[k] = f2.y;
    }
    float u0 = g_base[w * 128 + 64 + 2 * lane];
    float u1 = g_base[w * 128 + 64 + 2 * lane + 1];
    const float* rbase = g_r + (size_t)layer * EE * KH;
    for (int p = beg; p < beg + cnt; p++) {
        int e = g_csr[p];
        int d = dst[e];
        float rk = rbase[e * KH + lane];
        float a0 = u0, a1 = u1;
#pragma unroll
        for (int k = 0; k < 32; k++) {
            float rv = __shfl_sync(0xffffffffu, rk, k);
            a0 += rv * G0[k];
            a1 += rv * G1[k];
        }
        atomicAdd(&g_agg[d * H + 2 * lane], a0);
        atomicAdd(&g_agg[d * H + 2 * lane + 1], a1);
    }
}

// ===================== fused norm (single-wave coop) =====================
__global__ __launch_bounds__(256) void k_norm(int l, float* __restrict__ out,
                                              const float* __restrict__ rb,
                                              const float* __restrict__ gw,
                                              const float* __restrict__ gb,
                                              const float* __restrict__ gms) {
    __shared__ float rs[256], rs2[256];
    int tid = threadIdx.x;
    int o = tid & 63, g = tid >> 6;
    int nbase = blockIdx.x * 80;
    float vloc[20];
    float s = 0.0f, s2 = 0.0f;
#pragma unroll
    for (int j = 0; j < 20; j++) {
        int n = nbase + j * 4 + g;
        int idx = n * H + o;
        float v = g_agg[idx] * g_invdeg[n] + g_base[n * 128 + o] + rb[o];
        vloc[j] = v;
        s += v;
        s2 += v * v;
    }
    rs[tid] = s;
    rs2[tid] = s2;
    __syncthreads();
    if (tid < 64) {
        float t = rs[tid] + rs[tid + 64] + rs[tid + 128] + rs[tid + 192];
        float t2 = rs2[tid] + rs2[tid + 64] + rs2[tid + 128] + rs2[tid + 192];
        atomicAdd(&g_colsum[l][tid], t);
        atomicAdd(&g_colsumsq[l][tid], t2);
        __threadfence();
    }
    __syncthreads();
    if (tid == 0) {
        atomicAdd(&g_done[l], 1);
        while (atomicAdd(&g_done[l], 0) < NORMBLKS) {}
    }
    __syncthreads();
    volatile float* cs = g_colsum[l];
    volatile float* cs2 = g_colsumsq[l];
    float mean = cs[o] * (1.0f / NN);
    float ex2 = cs2[o] * (1.0f / NN);
    float ms = gms[o];
    float var = ex2 - (2.0f * ms - ms * ms) * mean * mean;
    float a = gw[o] * rsqrtf(var + GEPS);
    float cc = gb[o] - a * ms * mean;
#pragma unroll
    for (int j = 0; j < 20; j++) {
        int n = nbase + j * 4 + g;
        int idx = n * H + o;
        float v = a * vloc[j] + cc;
        if (l == 0) {
            v = (v > 0.0f) ? v : 0.2f * v;
            __half hi = __float2half_rn(v);
            __half lo = __float2half_rn(v - __half2float(hi));
            g_A[n * KB + o] = hi;
            g_A[n * KB + 64 + o] = lo;
            g_agg[idx] = 0.0f;
        } else {
            out[idx] = v;
        }
    }
}

// ===================== launch =====================
extern "C" void kernel_launch(void* const* d_in, const int* in_sizes, int n_in,
                              void* d_out, int out_size) {
    const float* x      = (const float*)d_in[0];
    const int*   ei     = (const int*)d_in[1];
    const float* ea     = (const float*)d_in[2];
    const float* proj_w = (const float*)d_in[3];
    const float* proj_b = (const float*)d_in[4];
    const float* enn_w1 = (const float*)d_in[5];
    const float* enn_b1 = (const float*)d_in[6];
    const float* enn_w2 = (const float*)d_in[7];
    const float* enn_b2 = (const float*)d_in[8];
    const float* root_w = (const float*)d_in[9];
    const float* root_b = (const float*)d_in[10];
    const float* gn_w   = (const float*)d_in[11];
    const float* gn_b   = (const float*)d_in[12];
    const float* gn_ms  = (const float*)d_in[13];
    const int* src = ei;
    const int* dst = ei + EE;

    cudaFuncSetAttribute(k_gemm, cudaFuncAttributeMaxDynamicSharedMemorySize, GSMEM);

    // launch #4 (= ncu capture slot) is k_gemm layer 0
    k_proj<<<(MPAD * H + 255) / 256, 256>>>(x, proj_w, proj_b);
    k_prep<<<(PREPTOT + 255) / 256, 256>>>(ea, enn_w1, enn_b1, enn_w2, root_w, enn_b2,
                                           src, dst);
    k_csr<<<CSRBLKS, 256>>>(src);
    k_gemm<<<dim3(40, 17), 256, GSMEM>>>(0);
    k_msg<<<(NN + 7) / 8, 256>>>(dst, 0);
    k_norm<<<NORMBLKS, 256>>>(0, (float*)d_out, root_b, gn_w, gn_b, gn_ms);
    k_gemm<<<dim3(40, 17), 256, GSMEM>>>(1);
    k_msg<<<(NN + 7) / 8, 256>>>(dst, 1);
    k_norm<<<NORMBLKS, 256>>>(1, (float*)d_out, root_b + H, gn_w + H, gn_b + H, gn_ms + H);
}